// round 10
// baseline (speedup 1.0000x reference)
#include <cuda_runtime.h>
#include <math.h>
#include <stdint.h>

#define BB 16
#define SEQL 1025
#define EMB 384
#define HDS 6
#define HD 64
#define NF 32
#define ROWS (BB*SEQL)
#define BHN (BB*HDS)
#define NT 17            // kv tiles of 64
#define NPAD (NT*64)     // 1088

__device__ float g_q[(size_t)BHN*SEQL*HD];   // [b,h,s,d]
__device__ float g_k[(size_t)BHN*SEQL*HD];
__device__ float g_v[(size_t)BHN*SEQL*HD];
__device__ float g_ao[(size_t)ROWS*EMB];
__device__ float g_cos[SEQL*HDS*NF];
__device__ float g_sin[SEQL*HDS*NF];
__device__ float g_freqs[HDS*NF*2];
// packed K fragments per (bh, tile): 2304 uint2
__device__ uint2    g_kp[(size_t)BHN*NT*2304];
// padded tf32 V per (bh, tile): 4608 words
__device__ uint32_t g_vp[(size_t)BHN*NT*4608];
// packed weights: [mat(4)][cb(6)][chunk(6)] x 2304 uint4 (hi0,hi4,lo0,lo4)
__device__ uint4    g_wp[(size_t)4*6*6*2304];

// ===================== mma.sync helpers =====================
__device__ __forceinline__ uint32_t f2tf32(float x) {
    uint32_t r;
    asm("cvt.rna.tf32.f32 %0, %1;" : "=r"(r) : "f"(x));
    return r;
}
__device__ __forceinline__ void mma_tf32(float* d, const uint32_t* a,
                                         uint32_t b0, uint32_t b1) {
    asm volatile(
        "mma.sync.aligned.m16n8k8.row.col.f32.tf32.tf32.f32 "
        "{%0,%1,%2,%3}, {%4,%5,%6,%7}, {%8,%9}, {%0,%1,%2,%3};"
        : "+f"(d[0]), "+f"(d[1]), "+f"(d[2]), "+f"(d[3])
        : "r"(a[0]), "r"(a[1]), "r"(a[2]), "r"(a[3]), "r"(b0), "r"(b1));
}
__device__ __forceinline__ uint32_t smem_to_u32(const void* p) {
    uint32_t a;
    asm("{ .reg .u64 t; cvta.to.shared.u64 t, %1; cvt.u32.u64 %0, t; }" : "=r"(a) : "l"(p));
    return a;
}
#define CP16(dst, src) \
    asm volatile("cp.async.cg.shared.global [%0], [%1], 16;" :: "r"(dst), "l"(src))
#define CP16Z(dst, src, sz) \
    asm volatile("cp.async.cg.shared.global [%0], [%1], 16, %2;" :: "r"(dst), "l"(src), "r"(sz))
#define CP_COMMIT() asm volatile("cp.async.commit_group;" ::: "memory")
#define CP_WAIT0()  asm volatile("cp.async.wait_group 0;" ::: "memory")

// ===================== init (bit-matched constants) =====================
__device__ __forceinline__ float erfinv_xla(float x) {
    float w = -log1pf(-__fmul_rn(x, x));
    float p;
    if (w < 5.0f) {
        w = w - 2.5f;
        p = 2.81022636e-08f;
        p = fmaf(p, w, 3.43273939e-07f);
        p = fmaf(p, w, -3.5233877e-06f);
        p = fmaf(p, w, -4.39150654e-06f);
        p = fmaf(p, w, 0.00021858087f);
        p = fmaf(p, w, -0.00125372503f);
        p = fmaf(p, w, -0.00417768164f);
        p = fmaf(p, w, 0.246640727f);
        p = fmaf(p, w, 1.50140941f);
    } else {
        w = sqrtf(w) - 3.0f;
        p = -0.000200214257f;
        p = fmaf(p, w, 0.000100950558f);
        p = fmaf(p, w, 0.00134934322f);
        p = fmaf(p, w, -0.00367342844f);
        p = fmaf(p, w, 0.00573950773f);
        p = fmaf(p, w, -0.0076224613f);
        p = fmaf(p, w, 0.00943887047f);
        p = fmaf(p, w, 1.00167406f);
        p = fmaf(p, w, 2.83297682f);
    }
    return p * x;
}

__global__ void init_freqs(float inv_g) {
    int n = threadIdx.x;
    if (n >= HDS * NF) return;
    float alpha0 = powf(inv_g, 1.0f);
    float alpha1 = powf(inv_g, 2.0f);
    float fi = (float)(n + 1);
    float z0 = fmodf(__fmul_rn(fi, alpha0), 1.0f);
    float z1 = fmodf(__fmul_rn(fi, alpha1), 1.0f);
    float d0 = erfinv_xla(__fmul_rn(2.0f, z0) - 1.0f);
    float d1 = erfinv_xla(__fmul_rn(2.0f, z1) - 1.0f);
    float nrm = sqrtf(__fadd_rn(__fmul_rn(d0, d0), __fmul_rn(d1, d1)));
    d0 = __fdiv_rn(d0, nrm);
    d1 = __fdiv_rn(d1, nrm);
    int f = n % NF;
    float t = __fmul_rn((float)f, (1.0f / 31.0f));
    float omega = __fmul_rn(0.1f, powf(10000.0f, t));
    g_freqs[n * 2 + 0] = __fmul_rn(d0, omega);
    g_freqs[n * 2 + 1] = __fmul_rn(d1, omega);
}

__global__ void init_trig() {
    int idx = blockIdx.x * blockDim.x + threadIdx.x;
    if (idx >= SEQL * HDS * NF) return;
    int s = idx / (HDS * NF);
    int r = idx % (HDS * NF);
    float c0 = 0.f, c1 = 0.f;
    if (s > 0) {
        int p = s - 1;
        int xi = p % 32, yi = p / 32;
        c0 = __fmul_rn(__fdiv_rn((float)xi, 31.0f), 2.0f) - 1.0f;
        c1 = __fmul_rn(__fdiv_rn((float)yi, 31.0f), 2.0f) - 1.0f;
    }
    float th = __fadd_rn(__fmul_rn(g_freqs[r * 2 + 0], c0), __fmul_rn(g_freqs[r * 2 + 1], c1));
    g_cos[idx] = cosf(th);
    g_sin[idx] = sinf(th);
}

// ===================== one-shot pack kernels =====================
__global__ void __launch_bounds__(256) pack_w_kernel(
    const float* __restrict__ Wq, const float* __restrict__ Wk,
    const float* __restrict__ Wv, const float* __restrict__ Wo)
{
    int idx = blockIdx.x * 256 + threadIdx.x;
    if (idx >= 4 * 36 * 512) return;
    int t = idx & 511;
    int n = t & 63, ks = t >> 6;
    int r = idx >> 9;                   // mat*36 + cb*6 + c
    int mat = r / 36;
    int rem = r % 36;
    int cb = rem / 6, c = rem % 6;
    const float* W = (mat == 0) ? Wq : (mat == 1) ? Wk : (mat == 2) ? Wv : Wo;
    int colbase = cb * 64, k0 = c * 64;
    float wv[8];
#pragma unroll
    for (int j = 0; j < 8; j++)
        wv[j] = W[(size_t)(k0 + 8 * ks + j) * EMB + colbase + n];
    uint32_t hi[8], lo[8];
#pragma unroll
    for (int j = 0; j < 8; j++) {
        hi[j] = f2tf32(wv[j]);
        lo[j] = f2tf32(wv[j] - __uint_as_float(hi[j]));
    }
    uint4* dst = g_wp + (size_t)r * 2304 + n * 36 + ks * 4;
    dst[0] = make_uint4(hi[0], hi[4], lo[0], lo[4]);
    dst[1] = make_uint4(hi[1], hi[5], lo[1], lo[5]);
    dst[2] = make_uint4(hi[2], hi[6], lo[2], lo[6]);
    dst[3] = make_uint4(hi[3], hi[7], lo[3], lo[7]);
}

__global__ void __launch_bounds__(256) pack_k_kernel() {
    int idx = blockIdx.x * 256 + threadIdx.x;
    if (idx >= BHN * NPAD * 8) return;
    int ks = idx & 7;
    int tmp = idx >> 3;
    int n = tmp % NPAD;
    int bh = tmp / NPAD;
    float4 ka = make_float4(0.f, 0.f, 0.f, 0.f);
    float4 kb = make_float4(0.f, 0.f, 0.f, 0.f);
    if (n < SEQL) {
        const float* K = g_k + ((size_t)bh * SEQL + n) * HD + 8 * ks;
        ka = *(const float4*)K;
        kb = *(const float4*)(K + 4);
    }
    uint2* dst = g_kp + ((size_t)bh * NT + (n >> 6)) * 2304 + (n & 63) * 36 + ks * 4;
    dst[0] = make_uint2(f2tf32(ka.x), f2tf32(kb.x));
    dst[1] = make_uint2(f2tf32(ka.y), f2tf32(kb.y));
    dst[2] = make_uint2(f2tf32(ka.z), f2tf32(kb.z));
    dst[3] = make_uint2(f2tf32(ka.w), f2tf32(kb.w));
}

__global__ void __launch_bounds__(256) pack_v_kernel() {
    int idx = blockIdx.x * 256 + threadIdx.x;
    if (idx >= BHN * NPAD * 18) return;
    int c4 = idx % 18;
    int tmp = idx / 18;
    int n = tmp % NPAD;
    int bh = tmp / NPAD;
    uint4 val = make_uint4(0u, 0u, 0u, 0u);
    if (c4 < 16 && n < SEQL) {
        float4 v = *(const float4*)(g_v + ((size_t)bh * SEQL + n) * HD + 4 * c4);
        val = make_uint4(f2tf32(v.x), f2tf32(v.y), f2tf32(v.z), f2tf32(v.w));
    }
    *(uint4*)(g_vp + ((size_t)bh * NT + (n >> 6)) * 4608 + (n & 63) * 72 + c4 * 4) = val;
}

// ===================== tensorized GEMM v2 (cp.async + pre-packed W) =========
#define GW_OFF 8704
#define GEMM_SMEM ((8704 + 9216) * 4)   // 71680 B

struct GemmAcc { float o[8][4]; };

__device__ __forceinline__ void gemm_issue_x(
    const float* src, int row0, int c, uint32_t sbase, int tid)
{
#pragma unroll
    for (int u = 0; u < 8; u++) {
        int idx = tid + 256 * u;
        int rr = idx >> 4, c4 = idx & 15;
        int gr = row0 + rr;
        int ok = (gr < ROWS);
        int gc = ok ? gr : (ROWS - 1);
        uint32_t dst = sbase + (rr * 68 + 4 * c4) * 4;
        const char* s = (const char*)(src + (size_t)gc * EMB + c * 64 + 4 * c4);
        CP16Z(dst, s, ok ? 16 : 0);
    }
}
__device__ __forceinline__ void gemm_issue_w(
    const uint4* wp, int c, uint32_t sbase, int tid)
{
    const char* ws = (const char*)(wp + (size_t)c * 2304);
    uint32_t wd = sbase + GW_OFF * 4;
#pragma unroll
    for (int i = 0; i < 9; i++) {
        int off = (tid + 256 * i) * 16;
        CP16(wd + off, ws + off);
    }
}

__device__ __forceinline__ void gemm_core_v2(
    const float* __restrict__ src, const uint4* __restrict__ wp,
    int row0, float* xs, GemmAcc& A)
{
    int tid = threadIdx.x;
    int wid = tid >> 5, lane = tid & 31;
    int g = lane >> 2, tig = lane & 3;
    int wrow = wid * 16;
    uint32_t sbase = smem_to_u32(xs);
    uint4* Wp = (uint4*)(xs + GW_OFF);

    gemm_issue_x(src, row0, 0, sbase, tid);
    gemm_issue_w(wp, 0, sbase, tid);
    CP_COMMIT();

#pragma unroll
    for (int c = 0; c < 6; c++) {
        CP_WAIT0();
        __syncthreads();

#pragma unroll
        for (int ks = 0; ks < 8; ks++) {
            float a0 = xs[(wrow + g) * 68 + 8 * ks + tig];
            float a1 = xs[(wrow + g + 8) * 68 + 8 * ks + tig];
            float a2 = xs[(wrow + g) * 68 + 8 * ks + tig + 4];
            float a3 = xs[(wrow + g + 8) * 68 + 8 * ks + tig + 4];
            uint32_t ahi[4], alo[4];
            ahi[0] = f2tf32(a0); alo[0] = f2tf32(a0 - __uint_as_float(ahi[0]));
            ahi[1] = f2tf32(a1); alo[1] = f2tf32(a1 - __uint_as_float(ahi[1]));
            ahi[2] = f2tf32(a2); alo[2] = f2tf32(a2 - __uint_as_float(ahi[2]));
            ahi[3] = f2tf32(a3); alo[3] = f2tf32(a3 - __uint_as_float(ahi[3]));
#pragma unroll
            for (int nb = 0; nb < 8; nb++) {
                uint4 w4 = Wp[(nb * 8 + g) * 36 + ks * 4 + tig];
                mma_tf32(A.o[nb], ahi, w4.x, w4.y);
                mma_tf32(A.o[nb], ahi, w4.z, w4.w);
                mma_tf32(A.o[nb], alo, w4.x, w4.y);
            }
        }
        __syncthreads();
        if (c < 5) {
            gemm_issue_x(src, row0, c + 1, sbase, tid);
            gemm_issue_w(wp, c + 1, sbase, tid);
            CP_COMMIT();
        }
    }
}

__global__ void __launch_bounds__(256) qkv_mma_kernel(const float* __restrict__ x)
{
    extern __shared__ float sm[];
    int tid = threadIdx.x;
    int wid = tid >> 5, lane = tid & 31;
    int g = lane >> 2, tig = lane & 3;
    int wrow = wid * 16;
    int rb = blockIdx.x, h = blockIdx.y, z = blockIdx.z;
    int row0 = rb * 128;
    const uint4* wp = g_wp + ((size_t)z * 6 + h) * 6 * 2304;

    GemmAcc A;
#pragma unroll
    for (int nb = 0; nb < 8; nb++)
#pragma unroll
        for (int j = 0; j < 4; j++) A.o[nb][j] = 0.f;

    gemm_core_v2(x, wp, row0, sm, A);

    if (z < 2) {
        float* base = (z == 0) ? g_q : g_k;
#pragma unroll
        for (int nb = 0; nb < 4; nb++)
#pragma unroll
            for (int jj = 0; jj < 4; jj++) {
                int gr = row0 + wrow + g + 8 * (jj >> 1);
                if (gr >= ROWS) continue;
                int b = gr / SEQL, s = gr % SEQL;
                int f = 8 * nb + 2 * tig + (jj & 1);
                float cv = g_cos[(s * HDS + h) * NF + f];
                float sv = g_sin[(s * HDS + h) * NF + f];
                float lov = A.o[nb][jj], hiv = A.o[nb + 4][jj];
                float* dst = base + ((size_t)(b * HDS + h) * SEQL + s) * HD;
                dst[f]      = lov * cv - hiv * sv;
                dst[f + 32] = lov * sv + hiv * cv;
            }
    } else {
#pragma unroll
        for (int nb = 0; nb < 8; nb++)
#pragma unroll
            for (int jj = 0; jj < 4; jj++) {
                int gr = row0 + wrow + g + 8 * (jj >> 1);
                if (gr >= ROWS) continue;
                int b = gr / SEQL, s = gr % SEQL;
                int col = 8 * nb + 2 * tig + (jj & 1);
                g_v[((size_t)(b * HDS + h) * SEQL + s) * HD + col] = A.o[nb][jj];
            }
    }
}

__global__ void __launch_bounds__(256) proj_mma_kernel(
    const float* __restrict__ bo, float* __restrict__ out)
{
    extern __shared__ float sm[];
    int tid = threadIdx.x;
    int wid = tid >> 5, lane = tid & 31;
    int g = lane >> 2, tig = lane & 3;
    int wrow = wid * 16;
    int rb = blockIdx.x, cb = blockIdx.y;
    int row0 = rb * 128, colbase = cb * 64;
    const uint4* wp = g_wp + ((size_t)3 * 6 + cb) * 6 * 2304;

    GemmAcc A;
#pragma unroll
    for (int nb = 0; nb < 8; nb++)
#pragma unroll
        for (int j = 0; j < 4; j++) A.o[nb][j] = 0.f;

    gemm_core_v2(g_ao, wp, row0, sm, A);

#pragma unroll
    for (int nb = 0; nb < 8; nb++)
#pragma unroll
        for (int jj = 0; jj < 4; jj++) {
            int gr = row0 + wrow + g + 8 * (jj >> 1);
            if (gr >= ROWS) continue;
            int col = 8 * nb + 2 * tig + (jj & 1);
            out[(size_t)gr * EMB + colbase + col] = A.o[nb][jj] + bo[colbase + col];
        }
}

// ===================== Flash attention (cp.async pipelined) =================
#define PS_OFF 0
#define KP_OFF 4352
#define V0_OFF 8960
#define V1_OFF 13568
#define ATTN_SMEM (18176 * 4)   // 72704 B

__global__ void __launch_bounds__(128, 3) attn_mma_kernel() {
    extern __shared__ float sm[];
    float* Ps = sm + PS_OFF;
    uint32_t sbase = smem_to_u32(sm);

    int tid = threadIdx.x;
    int wid = tid >> 5, lane = tid & 31;
    int g = lane >> 2, tig = lane & 3;
    int wrow = wid * 16;
    int qb = blockIdx.x, bh = blockIdx.y;

    const float* Q = g_q + (size_t)bh * SEQL * HD;
    const char* gk = (const char*)(g_kp + (size_t)bh * NT * 2304);
    const char* gv = (const char*)(g_vp + (size_t)bh * NT * 4608);

    const uint32_t KPA = sbase + KP_OFF * 4;
    const uint32_t VA[2] = { sbase + V0_OFF * 4, sbase + V1_OFF * 4 };

#pragma unroll
    for (int i = 0; i < 9; i++) {
        int off = (tid + 128 * i) * 16;
        CP16(KPA + off, gk + off);
        CP16(VA[0] + off, gv + off);
    }
    CP_COMMIT();

#pragma unroll
    for (int u = 0; u < 8; u++) {
        int idx = tid + 128 * u;
        int rr = idx >> 4, c4 = idx & 15;
        int s = qb * 64 + rr;
        float4 v = make_float4(0.f, 0.f, 0.f, 0.f);
        if (s < SEQL) v = *(const float4*)(Q + (size_t)s * HD + c4 * 4);
        v.x *= 0.125f; v.y *= 0.125f; v.z *= 0.125f; v.w *= 0.125f;
        *(float4*)(Ps + rr * 68 + c4 * 4) = v;
    }
    __syncthreads();

    uint32_t qhi[8][4];
#pragma unroll
    for (int ks = 0; ks < 8; ks++) {
#pragma unroll
        for (int j = 0; j < 4; j++) {
            int rr = wrow + g + (j & 1) * 8;
            int cc = 8 * ks + tig + (j >> 1) * 4;
            qhi[ks][j] = f2tf32(Ps[rr * 68 + cc]);
        }
    }

    float o[8][4] = {};
    float m0 = -INFINITY, m1 = -INFINITY, l0 = 0.f, l1 = 0.f;

    for (int t = 0; t < NT; t++) {
        CP_WAIT0();
        __syncthreads();

        if (t < NT - 1) {
            const char* vsrc = gv + (size_t)(t + 1) * 4608 * 4;
            uint32_t vdst = VA[(t + 1) & 1];
#pragma unroll
            for (int i = 0; i < 9; i++) {
                int off = (tid + 128 * i) * 16;
                CP16(vdst + off, vsrc + off);
            }
            CP_COMMIT();
        }

        uint2* Kp = (uint2*)(sm + KP_OFF);
        float s_[8][4] = {};
#pragma unroll
        for (int ks = 0; ks < 8; ks++) {
#pragma unroll
            for (int nb = 0; nb < 8; nb++) {
                uint2 kk = Kp[(nb * 8 + g) * 36 + ks * 4 + tig];
                mma_tf32(s_[nb], qhi[ks], kk.x, kk.y);
            }
        }
        __syncthreads();

        if (t < NT - 1) {
            const char* ksrc = gk + (size_t)(t + 1) * 2304 * 8;
#pragma unroll
            for (int i = 0; i < 9; i++) {
                int off = (tid + 128 * i) * 16;
                CP16(KPA + off, ksrc + off);
            }
            CP_COMMIT();
        }

        if (t == NT - 1) {
#pragma unroll
            for (int nb = 0; nb < 8; nb++) {
                int c = 1024 + nb * 8 + 2 * tig;
                if (c >= SEQL)     { s_[nb][0] = -INFINITY; s_[nb][2] = -INFINITY; }
                if (c + 1 >= SEQL) { s_[nb][1] = -INFINITY; s_[nb][3] = -INFINITY; }
            }
        }

        float rm0 = -INFINITY, rm1 = -INFINITY;
#pragma unroll
        for (int nb = 0; nb < 8; nb++) {
            rm0 = fmaxf(rm0, fmaxf(s_[nb][0], s_[nb][1]));
            rm1 = fmaxf(rm1, fmaxf(s_[nb][2], s_[nb][3]));
        }
        rm0 = fmaxf(rm0, __shfl_xor_sync(0xffffffffu, rm0, 1));
        rm0 = fmaxf(rm0, __shfl_xor_sync(0xffffffffu, rm0, 2));
        rm1 = fmaxf(rm1, __shfl_xor_sync(0xffffffffu, rm1, 1));
        rm1 = fmaxf(rm1, __shfl_xor_sync(0xffffffffu, rm1, 2));
        float nm0 = fmaxf(m0, rm0), nm1 = fmaxf(m1, rm1);
        float corr0 = __expf(m0 - nm0), corr1 = __expf(m1 - nm1);
        m0 = nm0; m1 = nm1;

        float rs0 = 0.f, rs1 = 0.f;
#pragma unroll
        for (int nb = 0; nb < 8; nb++) {
            s_[nb][0] = __expf(s_[nb][0] - m0);
            s_[nb][1] = __expf(s_[nb][1] - m0);
            s_[nb][2] = __expf(s_[nb][2] - m1);
            s_[nb][3] = __expf(s_[nb][3] - m1);
            rs0 += s_[nb][0] + s_[nb][1];
            rs1 += s_[nb][2] + s_[nb][3];
        }
        rs0 += __shfl_xor_sync(0xffffffffu, rs0, 1);
        rs0 += __shfl_xor_sync(0xffffffffu, rs0, 2);
        rs1 += __shfl_xor_sync(0xffffffffu, rs1, 1);
        rs1 += __shfl_xor_sync(0xffffffffu, rs1, 2);
        l0 = l0 * corr0 + rs0;
        l1 = l1 * corr1 + rs1;

#pragma unroll
        for (int nb = 0; nb < 8; nb++) {
            o[nb][0] *= corr0; o[nb][1] *= corr0;
            o[nb][2] *= corr1; o[nb][3] *= corr1;
        }

#pragma unroll
        for (int nb = 0; nb < 8; nb++) {
            *(float2*)(Ps + (wrow + g) * 68 + nb * 8 + 2 * tig)     = make_float2(s_[nb][0], s_[nb][1]);
            *(float2*)(Ps + (wrow + g + 8) * 68 + nb * 8 + 2 * tig) = make_float2(s_[nb][2], s_[nb][3]);
        }
        __syncwarp();

        uint32_t* Vs = (uint32_t*)(sm + ((t & 1) ? V1_OFF : V0_OFF));
#pragma unroll
        for (int ks = 0; ks < 8; ks++) {
            uint32_t pa[4];
            pa[0] = f2tf32(Ps[(wrow + g) * 68 + 8 * ks + tig]);
            pa[1] = f2tf32(Ps[(wrow + g + 8) * 68 + 8 * ks + tig]);
            pa[2] = f2tf32(Ps[(wrow + g) * 68 + 8 * ks + tig + 4]);
            pa[3] = f2tf32(Ps[(wrow + g + 8) * 68 + 8 * ks + tig + 4]);
#pragma unroll
            for (int nb = 0; nb < 8; nb++) {
                int r0 = 8 * ks + tig;
                int cc = nb * 8 + g;
                mma_tf32(o[nb], pa, Vs[r0 * 72 + cc], Vs[(r0 + 4) * 72 + cc]);
            }
        }
    }

    float inv0 = 1.0f / l0, inv1 = 1.0f / l1;
    int b = bh / HDS, h = bh % HDS;
    int s0 = qb * 64 + wrow + g;
    int s1 = s0 + 8;
#pragma unroll
    for (int nb = 0; nb < 8; nb++) {
        int cc = nb * 8 + 2 * tig;
        if (s0 < SEQL) {
            float* dst = g_ao + ((size_t)b * SEQL + s0) * EMB + h * HD + cc;
            *(float2*)dst = make_float2(o[nb][0] * inv0, o[nb][1] * inv0);
        }
        if (s1 < SEQL) {
            float* dst = g_ao + ((size_t)b * SEQL + s1) * EMB + h * HD + cc;
            *(float2*)dst = make_float2(o[nb][2] * inv1, o[nb][3] * inv1);
        }
    }
}

// ===================== launch =====================
extern "C" void kernel_launch(void* const* d_in, const int* in_sizes, int n_in,
                              void* d_out, int out_size)
{
    const float* x  = (const float*)d_in[0];
    const float* Wq = (const float*)d_in[1];
    const float* Wk = (const float*)d_in[2];
    const float* Wv = (const float*)d_in[3];
    const float* Wo = (const float*)d_in[4];
    const float* bo = (const float*)d_in[5];
    float* out = (float*)d_out;

    double xg = 2.0;
    for (int it = 0; it < 10; ++it) xg = pow(1.0 + xg, 1.0 / 3.0);
    float inv_g = (float)(1.0 / xg);

    cudaFuncSetAttribute(attn_mma_kernel,
                         cudaFuncAttributeMaxDynamicSharedMemorySize, ATTN_SMEM);
    cudaFuncSetAttribute(qkv_mma_kernel,
                         cudaFuncAttributeMaxDynamicSharedMemorySize, GEMM_SMEM);
    cudaFuncSetAttribute(proj_mma_kernel,
                         cudaFuncAttributeMaxDynamicSharedMemorySize, GEMM_SMEM);

    init_freqs<<<1, 192>>>(inv_g);
    init_trig<<<(SEQL * HDS * NF + 255) / 256, 256>>>();
    pack_w_kernel<<<(4 * 36 * 512 + 255) / 256, 256>>>(Wq, Wk, Wv, Wo);

    dim3 qkv_grid((ROWS + 127) / 128, HDS, 3);
    qkv_mma_kernel<<<qkv_grid, 256, GEMM_SMEM>>>(x);

    pack_k_kernel<<<(BHN * NPAD * 8 + 255) / 256, 256>>>();
    pack_v_kernel<<<(BHN * NPAD * 18 + 255) / 256, 256>>>();

    dim3 attn_grid(NT, BHN);
    attn_mma_kernel<<<attn_grid, 128, ATTN_SMEM>>>();

    dim3 proj_grid((ROWS + 127) / 128, EMB / 64);
    proj_mma_kernel<<<proj_grid, 256, GEMM_SMEM>>>(bo, out);
}

// round 11
// speedup vs baseline: 1.0500x; 1.0500x over previous
#include <cuda_runtime.h>
#include <math.h>
#include <stdint.h>

#define BB 16
#define SEQL 1025
#define EMB 384
#define HDS 6
#define HD 64
#define NF 32
#define ROWS (BB*SEQL)
#define BHN (BB*HDS)
#define NT 17            // kv tiles of 64
#define NPAD (NT*64)     // 1088

__device__ float g_q[(size_t)BHN*SEQL*HD];   // [b,h,s,d]
__device__ float g_k[(size_t)BHN*SEQL*HD];
__device__ float g_v[(size_t)BHN*SEQL*HD];
__device__ float g_ao[(size_t)ROWS*EMB];
__device__ float g_cos[SEQL*HDS*NF];
__device__ float g_sin[SEQL*HDS*NF];
__device__ float g_freqs[HDS*NF*2];
__device__ uint2    g_kp[(size_t)BHN*NT*2304];
__device__ uint32_t g_vp[(size_t)BHN*NT*4608];
__device__ uint4    g_wp[(size_t)4*6*6*2304];

// ===================== mma.sync helpers =====================
__device__ __forceinline__ uint32_t f2tf32(float x) {
    uint32_t r;
    asm("cvt.rna.tf32.f32 %0, %1;" : "=r"(r) : "f"(x));
    return r;
}
__device__ __forceinline__ void mma_tf32(float* d, const uint32_t* a,
                                         uint32_t b0, uint32_t b1) {
    asm volatile(
        "mma.sync.aligned.m16n8k8.row.col.f32.tf32.tf32.f32 "
        "{%0,%1,%2,%3}, {%4,%5,%6,%7}, {%8,%9}, {%0,%1,%2,%3};"
        : "+f"(d[0]), "+f"(d[1]), "+f"(d[2]), "+f"(d[3])
        : "r"(a[0]), "r"(a[1]), "r"(a[2]), "r"(a[3]), "r"(b0), "r"(b1));
}
__device__ __forceinline__ uint32_t smem_to_u32(const void* p) {
    uint32_t a;
    asm("{ .reg .u64 t; cvta.to.shared.u64 t, %1; cvt.u32.u64 %0, t; }" : "=r"(a) : "l"(p));
    return a;
}
#define CP16(dst, src) \
    asm volatile("cp.async.cg.shared.global [%0], [%1], 16;" :: "r"(dst), "l"(src))
#define CP16Z(dst, src, sz) \
    asm volatile("cp.async.cg.shared.global [%0], [%1], 16, %2;" :: "r"(dst), "l"(src), "r"(sz))
#define CP_COMMIT() asm volatile("cp.async.commit_group;" ::: "memory")
#define CP_WAIT0()  asm volatile("cp.async.wait_group 0;" ::: "memory")
#define CP_WAIT1()  asm volatile("cp.async.wait_group 1;" ::: "memory")

// ===================== init (bit-matched constants) =====================
__device__ __forceinline__ float erfinv_xla(float x) {
    float w = -log1pf(-__fmul_rn(x, x));
    float p;
    if (w < 5.0f) {
        w = w - 2.5f;
        p = 2.81022636e-08f;
        p = fmaf(p, w, 3.43273939e-07f);
        p = fmaf(p, w, -3.5233877e-06f);
        p = fmaf(p, w, -4.39150654e-06f);
        p = fmaf(p, w, 0.00021858087f);
        p = fmaf(p, w, -0.00125372503f);
        p = fmaf(p, w, -0.00417768164f);
        p = fmaf(p, w, 0.246640727f);
        p = fmaf(p, w, 1.50140941f);
    } else {
        w = sqrtf(w) - 3.0f;
        p = -0.000200214257f;
        p = fmaf(p, w, 0.000100950558f);
        p = fmaf(p, w, 0.00134934322f);
        p = fmaf(p, w, -0.00367342844f);
        p = fmaf(p, w, 0.00573950773f);
        p = fmaf(p, w, -0.0076224613f);
        p = fmaf(p, w, 0.00943887047f);
        p = fmaf(p, w, 1.00167406f);
        p = fmaf(p, w, 2.83297682f);
    }
    return p * x;
}

__global__ void init_freqs(float inv_g) {
    int n = threadIdx.x;
    if (n >= HDS * NF) return;
    float alpha0 = powf(inv_g, 1.0f);
    float alpha1 = powf(inv_g, 2.0f);
    float fi = (float)(n + 1);
    float z0 = fmodf(__fmul_rn(fi, alpha0), 1.0f);
    float z1 = fmodf(__fmul_rn(fi, alpha1), 1.0f);
    float d0 = erfinv_xla(__fmul_rn(2.0f, z0) - 1.0f);
    float d1 = erfinv_xla(__fmul_rn(2.0f, z1) - 1.0f);
    float nrm = sqrtf(__fadd_rn(__fmul_rn(d0, d0), __fmul_rn(d1, d1)));
    d0 = __fdiv_rn(d0, nrm);
    d1 = __fdiv_rn(d1, nrm);
    int f = n % NF;
    float t = __fmul_rn((float)f, (1.0f / 31.0f));
    float omega = __fmul_rn(0.1f, powf(10000.0f, t));
    g_freqs[n * 2 + 0] = __fmul_rn(d0, omega);
    g_freqs[n * 2 + 1] = __fmul_rn(d1, omega);
}

__global__ void init_trig() {
    int idx = blockIdx.x * blockDim.x + threadIdx.x;
    if (idx >= SEQL * HDS * NF) return;
    int s = idx / (HDS * NF);
    int r = idx % (HDS * NF);
    float c0 = 0.f, c1 = 0.f;
    if (s > 0) {
        int p = s - 1;
        int xi = p % 32, yi = p / 32;
        c0 = __fmul_rn(__fdiv_rn((float)xi, 31.0f), 2.0f) - 1.0f;
        c1 = __fmul_rn(__fdiv_rn((float)yi, 31.0f), 2.0f) - 1.0f;
    }
    float th = __fadd_rn(__fmul_rn(g_freqs[r * 2 + 0], c0), __fmul_rn(g_freqs[r * 2 + 1], c1));
    g_cos[idx] = cosf(th);
    g_sin[idx] = sinf(th);
}

// ===================== one-shot pack kernels =====================
__global__ void __launch_bounds__(256) pack_w_kernel(
    const float* __restrict__ Wq, const float* __restrict__ Wk,
    const float* __restrict__ Wv, const float* __restrict__ Wo)
{
    int idx = blockIdx.x * 256 + threadIdx.x;
    if (idx >= 4 * 36 * 512) return;
    int t = idx & 511;
    int n = t & 63, ks = t >> 6;
    int r = idx >> 9;
    int mat = r / 36;
    int rem = r % 36;
    int cb = rem / 6, c = rem % 6;
    const float* W = (mat == 0) ? Wq : (mat == 1) ? Wk : (mat == 2) ? Wv : Wo;
    int colbase = cb * 64, k0 = c * 64;
    float wv[8];
#pragma unroll
    for (int j = 0; j < 8; j++)
        wv[j] = W[(size_t)(k0 + 8 * ks + j) * EMB + colbase + n];
    uint32_t hi[8], lo[8];
#pragma unroll
    for (int j = 0; j < 8; j++) {
        hi[j] = f2tf32(wv[j]);
        lo[j] = f2tf32(wv[j] - __uint_as_float(hi[j]));
    }
    uint4* dst = g_wp + (size_t)r * 2304 + n * 36 + ks * 4;
    dst[0] = make_uint4(hi[0], hi[4], lo[0], lo[4]);
    dst[1] = make_uint4(hi[1], hi[5], lo[1], lo[5]);
    dst[2] = make_uint4(hi[2], hi[6], lo[2], lo[6]);
    dst[3] = make_uint4(hi[3], hi[7], lo[3], lo[7]);
}

__global__ void __launch_bounds__(256) pack_k_kernel() {
    int idx = blockIdx.x * 256 + threadIdx.x;
    if (idx >= BHN * NPAD * 8) return;
    int ks = idx & 7;
    int tmp = idx >> 3;
    int n = tmp % NPAD;
    int bh = tmp / NPAD;
    float4 ka = make_float4(0.f, 0.f, 0.f, 0.f);
    float4 kb = make_float4(0.f, 0.f, 0.f, 0.f);
    if (n < SEQL) {
        const float* K = g_k + ((size_t)bh * SEQL + n) * HD + 8 * ks;
        ka = *(const float4*)K;
        kb = *(const float4*)(K + 4);
    }
    uint2* dst = g_kp + ((size_t)bh * NT + (n >> 6)) * 2304 + (n & 63) * 36 + ks * 4;
    dst[0] = make_uint2(f2tf32(ka.x), f2tf32(kb.x));
    dst[1] = make_uint2(f2tf32(ka.y), f2tf32(kb.y));
    dst[2] = make_uint2(f2tf32(ka.z), f2tf32(kb.z));
    dst[3] = make_uint2(f2tf32(ka.w), f2tf32(kb.w));
}

__global__ void __launch_bounds__(256) pack_v_kernel() {
    int idx = blockIdx.x * 256 + threadIdx.x;
    if (idx >= BHN * NPAD * 18) return;
    int c4 = idx % 18;
    int tmp = idx / 18;
    int n = tmp % NPAD;
    int bh = tmp / NPAD;
    uint4 val = make_uint4(0u, 0u, 0u, 0u);
    if (c4 < 16 && n < SEQL) {
        float4 v = *(const float4*)(g_v + ((size_t)bh * SEQL + n) * HD + 4 * c4);
        val = make_uint4(f2tf32(v.x), f2tf32(v.y), f2tf32(v.z), f2tf32(v.w));
    }
    *(uint4*)(g_vp + ((size_t)bh * NT + (n >> 6)) * 4608 + (n & 63) * 72 + c4 * 4) = val;
}

// ===================== tensorized GEMM v3 (double-buffered cp.async) ========
// buffer b (b=0,1): xs at BUF(b), Wp at BUF(b)+8704 ; BUF stride 17920 words
#define GBUF_W 17920
#define GW_OFF 8704
#define GEMM_SMEM (2 * GBUF_W * 4)   // 143360 B

struct GemmAcc { float o[8][4]; };

__device__ __forceinline__ void gemm_issue(
    const float* src, const uint4* wp, int row0, int c,
    uint32_t sbase, int buf, int tid)
{
    uint32_t base = sbase + (buf ? GBUF_W * 4 : 0);
#pragma unroll
    for (int u = 0; u < 8; u++) {
        int idx = tid + 256 * u;
        int rr = idx >> 4, c4 = idx & 15;
        int gr = row0 + rr;
        int ok = (gr < ROWS);
        int gc = ok ? gr : (ROWS - 1);
        uint32_t dst = base + (rr * 68 + 4 * c4) * 4;
        const char* s = (const char*)(src + (size_t)gc * EMB + c * 64 + 4 * c4);
        CP16Z(dst, s, ok ? 16 : 0);
    }
    const char* ws = (const char*)(wp + (size_t)c * 2304);
    uint32_t wd = base + GW_OFF * 4;
#pragma unroll
    for (int i = 0; i < 9; i++) {
        int off = (tid + 256 * i) * 16;
        CP16(wd + off, ws + off);
    }
}

__device__ __forceinline__ void gemm_core_v3(
    const float* __restrict__ src, const uint4* __restrict__ wp,
    int row0, float* sm, GemmAcc& A)
{
    int tid = threadIdx.x;
    int wid = tid >> 5, lane = tid & 31;
    int g = lane >> 2, tig = lane & 3;
    int wrow = wid * 16;
    uint32_t sbase = smem_to_u32(sm);

    gemm_issue(src, wp, row0, 0, sbase, 0, tid);
    CP_COMMIT();

#pragma unroll
    for (int c = 0; c < 6; c++) {
        if (c < 5) {
            gemm_issue(src, wp, row0, c + 1, sbase, (c + 1) & 1, tid);
            CP_COMMIT();
            CP_WAIT1();
        } else {
            CP_WAIT0();
        }
        __syncthreads();

        float* xs = sm + ((c & 1) ? GBUF_W : 0);
        uint4* Wp = (uint4*)(xs + GW_OFF);
#pragma unroll
        for (int ks = 0; ks < 8; ks++) {
            float a0 = xs[(wrow + g) * 68 + 8 * ks + tig];
            float a1 = xs[(wrow + g + 8) * 68 + 8 * ks + tig];
            float a2 = xs[(wrow + g) * 68 + 8 * ks + tig + 4];
            float a3 = xs[(wrow + g + 8) * 68 + 8 * ks + tig + 4];
            uint32_t ahi[4], alo[4];
            ahi[0] = f2tf32(a0); alo[0] = f2tf32(a0 - __uint_as_float(ahi[0]));
            ahi[1] = f2tf32(a1); alo[1] = f2tf32(a1 - __uint_as_float(ahi[1]));
            ahi[2] = f2tf32(a2); alo[2] = f2tf32(a2 - __uint_as_float(ahi[2]));
            ahi[3] = f2tf32(a3); alo[3] = f2tf32(a3 - __uint_as_float(ahi[3]));
#pragma unroll
            for (int nb = 0; nb < 8; nb++) {
                uint4 w4 = Wp[(nb * 8 + g) * 36 + ks * 4 + tig];
                mma_tf32(A.o[nb], ahi, w4.x, w4.y);
                mma_tf32(A.o[nb], ahi, w4.z, w4.w);
                mma_tf32(A.o[nb], alo, w4.x, w4.y);
            }
        }
        __syncthreads();   // all reads of buffer c&1 done before it is refilled
    }
}

__global__ void __launch_bounds__(256) qkv_mma_kernel(const float* __restrict__ x)
{
    extern __shared__ float sm[];
    int tid = threadIdx.x;
    int wid = tid >> 5, lane = tid & 31;
    int g = lane >> 2, tig = lane & 3;
    int wrow = wid * 16;
    int rb = blockIdx.x, h = blockIdx.y, z = blockIdx.z;
    int row0 = rb * 128;
    const uint4* wp = g_wp + ((size_t)z * 6 + h) * 6 * 2304;

    GemmAcc A;
#pragma unroll
    for (int nb = 0; nb < 8; nb++)
#pragma unroll
        for (int j = 0; j < 4; j++) A.o[nb][j] = 0.f;

    gemm_core_v3(x, wp, row0, sm, A);

    if (z < 2) {
        float* base = (z == 0) ? g_q : g_k;
#pragma unroll
        for (int nb = 0; nb < 4; nb++)
#pragma unroll
            for (int jj = 0; jj < 4; jj++) {
                int gr = row0 + wrow + g + 8 * (jj >> 1);
                if (gr >= ROWS) continue;
                int b = gr / SEQL, s = gr % SEQL;
                int f = 8 * nb + 2 * tig + (jj & 1);
                float cv = g_cos[(s * HDS + h) * NF + f];
                float sv = g_sin[(s * HDS + h) * NF + f];
                float lov = A.o[nb][jj], hiv = A.o[nb + 4][jj];
                float* dst = base + ((size_t)(b * HDS + h) * SEQL + s) * HD;
                dst[f]      = lov * cv - hiv * sv;
                dst[f + 32] = lov * sv + hiv * cv;
            }
    } else {
#pragma unroll
        for (int nb = 0; nb < 8; nb++)
#pragma unroll
            for (int jj = 0; jj < 4; jj++) {
                int gr = row0 + wrow + g + 8 * (jj >> 1);
                if (gr >= ROWS) continue;
                int b = gr / SEQL, s = gr % SEQL;
                int col = 8 * nb + 2 * tig + (jj & 1);
                g_v[((size_t)(b * HDS + h) * SEQL + s) * HD + col] = A.o[nb][jj];
            }
    }
}

__global__ void __launch_bounds__(256) proj_mma_kernel(
    const float* __restrict__ bo, float* __restrict__ out)
{
    extern __shared__ float sm[];
    int tid = threadIdx.x;
    int wid = tid >> 5, lane = tid & 31;
    int g = lane >> 2, tig = lane & 3;
    int wrow = wid * 16;
    int rb = blockIdx.x, cb = blockIdx.y;
    int row0 = rb * 128, colbase = cb * 64;
    const uint4* wp = g_wp + ((size_t)3 * 6 + cb) * 6 * 2304;

    GemmAcc A;
#pragma unroll
    for (int nb = 0; nb < 8; nb++)
#pragma unroll
        for (int j = 0; j < 4; j++) A.o[nb][j] = 0.f;

    gemm_core_v3(g_ao, wp, row0, sm, A);

#pragma unroll
    for (int nb = 0; nb < 8; nb++)
#pragma unroll
        for (int jj = 0; jj < 4; jj++) {
            int gr = row0 + wrow + g + 8 * (jj >> 1);
            if (gr >= ROWS) continue;
            int col = 8 * nb + 2 * tig + (jj & 1);
            out[(size_t)gr * EMB + colbase + col] = A.o[nb][jj] + bo[colbase + col];
        }
}

// ===================== Flash attention (cp.async pipelined) =================
#define PS_OFF 0
#define KP_OFF 4352
#define V0_OFF 8960
#define V1_OFF 13568
#define ATTN_SMEM (18176 * 4)   // 72704 B

__global__ void __launch_bounds__(128, 3) attn_mma_kernel() {
    extern __shared__ float sm[];
    float* Ps = sm + PS_OFF;
    uint32_t sbase = smem_to_u32(sm);

    int tid = threadIdx.x;
    int wid = tid >> 5, lane = tid & 31;
    int g = lane >> 2, tig = lane & 3;
    int wrow = wid * 16;
    int qb = blockIdx.x, bh = blockIdx.y;

    const float* Q = g_q + (size_t)bh * SEQL * HD;
    const char* gk = (const char*)(g_kp + (size_t)bh * NT * 2304);
    const char* gv = (const char*)(g_vp + (size_t)bh * NT * 4608);

    const uint32_t KPA = sbase + KP_OFF * 4;
    const uint32_t VA[2] = { sbase + V0_OFF * 4, sbase + V1_OFF * 4 };

#pragma unroll
    for (int i = 0; i < 9; i++) {
        int off = (tid + 128 * i) * 16;
        CP16(KPA + off, gk + off);
        CP16(VA[0] + off, gv + off);
    }
    CP_COMMIT();

#pragma unroll
    for (int u = 0; u < 8; u++) {
        int idx = tid + 128 * u;
        int rr = idx >> 4, c4 = idx & 15;
        int s = qb * 64 + rr;
        float4 v = make_float4(0.f, 0.f, 0.f, 0.f);
        if (s < SEQL) v = *(const float4*)(Q + (size_t)s * HD + c4 * 4);
        v.x *= 0.125f; v.y *= 0.125f; v.z *= 0.125f; v.w *= 0.125f;
        *(float4*)(Ps + rr * 68 + c4 * 4) = v;
    }
    __syncthreads();

    uint32_t qhi[8][4];
#pragma unroll
    for (int ks = 0; ks < 8; ks++) {
#pragma unroll
        for (int j = 0; j < 4; j++) {
            int rr = wrow + g + (j & 1) * 8;
            int cc = 8 * ks + tig + (j >> 1) * 4;
            qhi[ks][j] = f2tf32(Ps[rr * 68 + cc]);
        }
    }

    float o[8][4] = {};
    float m0 = -INFINITY, m1 = -INFINITY, l0 = 0.f, l1 = 0.f;

    for (int t = 0; t < NT; t++) {
        CP_WAIT0();
        __syncthreads();

        if (t < NT - 1) {
            const char* vsrc = gv + (size_t)(t + 1) * 4608 * 4;
            uint32_t vdst = VA[(t + 1) & 1];
#pragma unroll
            for (int i = 0; i < 9; i++) {
                int off = (tid + 128 * i) * 16;
                CP16(vdst + off, vsrc + off);
            }
            CP_COMMIT();
        }

        uint2* Kp = (uint2*)(sm + KP_OFF);
        float s_[8][4] = {};
#pragma unroll
        for (int ks = 0; ks < 8; ks++) {
#pragma unroll
            for (int nb = 0; nb < 8; nb++) {
                uint2 kk = Kp[(nb * 8 + g) * 36 + ks * 4 + tig];
                mma_tf32(s_[nb], qhi[ks], kk.x, kk.y);
            }
        }
        __syncthreads();

        if (t < NT - 1) {
            const char* ksrc = gk + (size_t)(t + 1) * 2304 * 8;
#pragma unroll
            for (int i = 0; i < 9; i++) {
                int off = (tid + 128 * i) * 16;
                CP16(KPA + off, ksrc + off);
            }
            CP_COMMIT();
        }

        if (t == NT - 1) {
#pragma unroll
            for (int nb = 0; nb < 8; nb++) {
                int c = 1024 + nb * 8 + 2 * tig;
                if (c >= SEQL)     { s_[nb][0] = -INFINITY; s_[nb][2] = -INFINITY; }
                if (c + 1 >= SEQL) { s_[nb][1] = -INFINITY; s_[nb][3] = -INFINITY; }
            }
        }

        float rm0 = -INFINITY, rm1 = -INFINITY;
#pragma unroll
        for (int nb = 0; nb < 8; nb++) {
            rm0 = fmaxf(rm0, fmaxf(s_[nb][0], s_[nb][1]));
            rm1 = fmaxf(rm1, fmaxf(s_[nb][2], s_[nb][3]));
        }
        rm0 = fmaxf(rm0, __shfl_xor_sync(0xffffffffu, rm0, 1));
        rm0 = fmaxf(rm0, __shfl_xor_sync(0xffffffffu, rm0, 2));
        rm1 = fmaxf(rm1, __shfl_xor_sync(0xffffffffu, rm1, 1));
        rm1 = fmaxf(rm1, __shfl_xor_sync(0xffffffffu, rm1, 2));
        float nm0 = fmaxf(m0, rm0), nm1 = fmaxf(m1, rm1);
        float corr0 = __expf(m0 - nm0), corr1 = __expf(m1 - nm1);
        m0 = nm0; m1 = nm1;

        float rs0 = 0.f, rs1 = 0.f;
#pragma unroll
        for (int nb = 0; nb < 8; nb++) {
            s_[nb][0] = __expf(s_[nb][0] - m0);
            s_[nb][1] = __expf(s_[nb][1] - m0);
            s_[nb][2] = __expf(s_[nb][2] - m1);
            s_[nb][3] = __expf(s_[nb][3] - m1);
            rs0 += s_[nb][0] + s_[nb][1];
            rs1 += s_[nb][2] + s_[nb][3];
        }
        rs0 += __shfl_xor_sync(0xffffffffu, rs0, 1);
        rs0 += __shfl_xor_sync(0xffffffffu, rs0, 2);
        rs1 += __shfl_xor_sync(0xffffffffu, rs1, 1);
        rs1 += __shfl_xor_sync(0xffffffffu, rs1, 2);
        l0 = l0 * corr0 + rs0;
        l1 = l1 * corr1 + rs1;

#pragma unroll
        for (int nb = 0; nb < 8; nb++) {
            o[nb][0] *= corr0; o[nb][1] *= corr0;
            o[nb][2] *= corr1; o[nb][3] *= corr1;
        }

#pragma unroll
        for (int nb = 0; nb < 8; nb++) {
            *(float2*)(Ps + (wrow + g) * 68 + nb * 8 + 2 * tig)     = make_float2(s_[nb][0], s_[nb][1]);
            *(float2*)(Ps + (wrow + g + 8) * 68 + nb * 8 + 2 * tig) = make_float2(s_[nb][2], s_[nb][3]);
        }
        __syncwarp();

        uint32_t* Vs = (uint32_t*)(sm + ((t & 1) ? V1_OFF : V0_OFF));
#pragma unroll
        for (int ks = 0; ks < 8; ks++) {
            uint32_t pa[4];
            pa[0] = f2tf32(Ps[(wrow + g) * 68 + 8 * ks + tig]);
            pa[1] = f2tf32(Ps[(wrow + g + 8) * 68 + 8 * ks + tig]);
            pa[2] = f2tf32(Ps[(wrow + g) * 68 + 8 * ks + tig + 4]);
            pa[3] = f2tf32(Ps[(wrow + g + 8) * 68 + 8 * ks + tig + 4]);
#pragma unroll
            for (int nb = 0; nb < 8; nb++) {
                int r0 = 8 * ks + tig;
                int cc = nb * 8 + g;
                mma_tf32(o[nb], pa, Vs[r0 * 72 + cc], Vs[(r0 + 4) * 72 + cc]);
            }
        }
    }

    float inv0 = 1.0f / l0, inv1 = 1.0f / l1;
    int b = bh / HDS, h = bh % HDS;
    int s0 = qb * 64 + wrow + g;
    int s1 = s0 + 8;
#pragma unroll
    for (int nb = 0; nb < 8; nb++) {
        int cc = nb * 8 + 2 * tig;
        if (s0 < SEQL) {
            float* dst = g_ao + ((size_t)b * SEQL + s0) * EMB + h * HD + cc;
            *(float2*)dst = make_float2(o[nb][0] * inv0, o[nb][1] * inv0);
        }
        if (s1 < SEQL) {
            float* dst = g_ao + ((size_t)b * SEQL + s1) * EMB + h * HD + cc;
            *(float2*)dst = make_float2(o[nb][2] * inv1, o[nb][3] * inv1);
        }
    }
}

// ===================== launch =====================
extern "C" void kernel_launch(void* const* d_in, const int* in_sizes, int n_in,
                              void* d_out, int out_size)
{
    const float* x  = (const float*)d_in[0];
    const float* Wq = (const float*)d_in[1];
    const float* Wk = (const float*)d_in[2];
    const float* Wv = (const float*)d_in[3];
    const float* Wo = (const float*)d_in[4];
    const float* bo = (const float*)d_in[5];
    float* out = (float*)d_out;

    double xg = 2.0;
    for (int it = 0; it < 10; ++it) xg = pow(1.0 + xg, 1.0 / 3.0);
    float inv_g = (float)(1.0 / xg);

    cudaFuncSetAttribute(attn_mma_kernel,
                         cudaFuncAttributeMaxDynamicSharedMemorySize, ATTN_SMEM);
    cudaFuncSetAttribute(qkv_mma_kernel,
                         cudaFuncAttributeMaxDynamicSharedMemorySize, GEMM_SMEM);
    cudaFuncSetAttribute(proj_mma_kernel,
                         cudaFuncAttributeMaxDynamicSharedMemorySize, GEMM_SMEM);

    init_freqs<<<1, 192>>>(inv_g);
    init_trig<<<(SEQL * HDS * NF + 255) / 256, 256>>>();
    pack_w_kernel<<<(4 * 36 * 512 + 255) / 256, 256>>>(Wq, Wk, Wv, Wo);

    dim3 qkv_grid((ROWS + 127) / 128, HDS, 3);
    qkv_mma_kernel<<<qkv_grid, 256, GEMM_SMEM>>>(x);

    pack_k_kernel<<<(BHN * NPAD * 8 + 255) / 256, 256>>>();
    pack_v_kernel<<<(BHN * NPAD * 18 + 255) / 256, 256>>>();

    dim3 attn_grid(NT, BHN);
    attn_mma_kernel<<<attn_grid, 128, ATTN_SMEM>>>();

    dim3 proj_grid((ROWS + 127) / 128, EMB / 64);
    proj_mma_kernel<<<proj_grid, 256, GEMM_SMEM>>>(bo, out);
}

// round 12
// speedup vs baseline: 1.2060x; 1.1485x over previous
#include <cuda_runtime.h>
#include <math.h>
#include <stdint.h>

#define BB 16
#define SEQL 1025
#define EMB 384
#define HDS 6
#define HD 64
#define NF 32
#define ROWS (BB*SEQL)
#define BHN (BB*HDS)
#define NT 17
#define NPAD (NT*64)

__device__ float g_q[(size_t)BHN*SEQL*HD];
__device__ float g_k[(size_t)BHN*SEQL*HD];
__device__ float g_v[(size_t)BHN*SEQL*HD];
__device__ float g_ao[(size_t)ROWS*EMB];
__device__ float g_cos[SEQL*HDS*NF];
__device__ float g_sin[SEQL*HDS*NF];
__device__ float g_freqs[HDS*NF*2];
__device__ uint2    g_kp[(size_t)BHN*NT*2304];
__device__ uint32_t g_vp[(size_t)BHN*NT*4608];
// packed W, K=32 chunks: [mat*72 + cb*12 + c2] x (64 n x 20 uint4)
__device__ uint4    g_wp[(size_t)4*6*12*1280];

// ===================== mma.sync helpers =====================
__device__ __forceinline__ uint32_t f2tf32(float x) {
    uint32_t r;
    asm("cvt.rna.tf32.f32 %0, %1;" : "=r"(r) : "f"(x));
    return r;
}
__device__ __forceinline__ void mma_tf32(float* d, const uint32_t* a,
                                         uint32_t b0, uint32_t b1) {
    asm volatile(
        "mma.sync.aligned.m16n8k8.row.col.f32.tf32.tf32.f32 "
        "{%0,%1,%2,%3}, {%4,%5,%6,%7}, {%8,%9}, {%0,%1,%2,%3};"
        : "+f"(d[0]), "+f"(d[1]), "+f"(d[2]), "+f"(d[3])
        : "r"(a[0]), "r"(a[1]), "r"(a[2]), "r"(a[3]), "r"(b0), "r"(b1));
}
__device__ __forceinline__ uint32_t smem_to_u32(const void* p) {
    uint32_t a;
    asm("{ .reg .u64 t; cvta.to.shared.u64 t, %1; cvt.u32.u64 %0, t; }" : "=r"(a) : "l"(p));
    return a;
}
#define CP16(dst, src) \
    asm volatile("cp.async.cg.shared.global [%0], [%1], 16;" :: "r"(dst), "l"(src))
#define CP16Z(dst, src, sz) \
    asm volatile("cp.async.cg.shared.global [%0], [%1], 16, %2;" :: "r"(dst), "l"(src), "r"(sz))
#define CP_COMMIT() asm volatile("cp.async.commit_group;" ::: "memory")
#define CP_WAIT0()  asm volatile("cp.async.wait_group 0;" ::: "memory")
#define CP_WAIT1()  asm volatile("cp.async.wait_group 1;" ::: "memory")

// ===================== init (bit-matched constants) =====================
__device__ __forceinline__ float erfinv_xla(float x) {
    float w = -log1pf(-__fmul_rn(x, x));
    float p;
    if (w < 5.0f) {
        w = w - 2.5f;
        p = 2.81022636e-08f;
        p = fmaf(p, w, 3.43273939e-07f);
        p = fmaf(p, w, -3.5233877e-06f);
        p = fmaf(p, w, -4.39150654e-06f);
        p = fmaf(p, w, 0.00021858087f);
        p = fmaf(p, w, -0.00125372503f);
        p = fmaf(p, w, -0.00417768164f);
        p = fmaf(p, w, 0.246640727f);
        p = fmaf(p, w, 1.50140941f);
    } else {
        w = sqrtf(w) - 3.0f;
        p = -0.000200214257f;
        p = fmaf(p, w, 0.000100950558f);
        p = fmaf(p, w, 0.00134934322f);
        p = fmaf(p, w, -0.00367342844f);
        p = fmaf(p, w, 0.00573950773f);
        p = fmaf(p, w, -0.0076224613f);
        p = fmaf(p, w, 0.00943887047f);
        p = fmaf(p, w, 1.00167406f);
        p = fmaf(p, w, 2.83297682f);
    }
    return p * x;
}

__global__ void init_freqs(float inv_g) {
    int n = threadIdx.x;
    if (n >= HDS * NF) return;
    float alpha0 = powf(inv_g, 1.0f);
    float alpha1 = powf(inv_g, 2.0f);
    float fi = (float)(n + 1);
    float z0 = fmodf(__fmul_rn(fi, alpha0), 1.0f);
    float z1 = fmodf(__fmul_rn(fi, alpha1), 1.0f);
    float d0 = erfinv_xla(__fmul_rn(2.0f, z0) - 1.0f);
    float d1 = erfinv_xla(__fmul_rn(2.0f, z1) - 1.0f);
    float nrm = sqrtf(__fadd_rn(__fmul_rn(d0, d0), __fmul_rn(d1, d1)));
    d0 = __fdiv_rn(d0, nrm);
    d1 = __fdiv_rn(d1, nrm);
    int f = n % NF;
    float t = __fmul_rn((float)f, (1.0f / 31.0f));
    float omega = __fmul_rn(0.1f, powf(10000.0f, t));
    g_freqs[n * 2 + 0] = __fmul_rn(d0, omega);
    g_freqs[n * 2 + 1] = __fmul_rn(d1, omega);
}

__global__ void init_trig() {
    int idx = blockIdx.x * blockDim.x + threadIdx.x;
    if (idx >= SEQL * HDS * NF) return;
    int s = idx / (HDS * NF);
    int r = idx % (HDS * NF);
    float c0 = 0.f, c1 = 0.f;
    if (s > 0) {
        int p = s - 1;
        int xi = p % 32, yi = p / 32;
        c0 = __fmul_rn(__fdiv_rn((float)xi, 31.0f), 2.0f) - 1.0f;
        c1 = __fmul_rn(__fdiv_rn((float)yi, 31.0f), 2.0f) - 1.0f;
    }
    float th = __fadd_rn(__fmul_rn(g_freqs[r * 2 + 0], c0), __fmul_rn(g_freqs[r * 2 + 1], c1));
    g_cos[idx] = cosf(th);
    g_sin[idx] = sinf(th);
}

// ===================== one-shot pack kernels =====================
__global__ void __launch_bounds__(256) pack_w_kernel(
    const float* __restrict__ Wq, const float* __restrict__ Wk,
    const float* __restrict__ Wv, const float* __restrict__ Wo)
{
    int idx = blockIdx.x * 256 + threadIdx.x;
    if (idx >= 4 * 72 * 256) return;           // 73728
    int ks = idx & 3;
    int n = (idx >> 2) & 63;
    int r2 = idx >> 8;                          // mat*72 + cb*12 + c2
    int mat = r2 / 72;
    int rem = r2 % 72;
    int cb = rem / 12, c2 = rem % 12;
    const float* W = (mat == 0) ? Wq : (mat == 1) ? Wk : (mat == 2) ? Wv : Wo;
    int colbase = cb * 64, k0 = c2 * 32;
    float wv[8];
#pragma unroll
    for (int j = 0; j < 8; j++)
        wv[j] = W[(size_t)(k0 + 8 * ks + j) * EMB + colbase + n];
    uint32_t hi[8], lo[8];
#pragma unroll
    for (int j = 0; j < 8; j++) {
        hi[j] = f2tf32(wv[j]);
        lo[j] = f2tf32(wv[j] - __uint_as_float(hi[j]));
    }
    uint4* dst = g_wp + (size_t)r2 * 1280 + n * 20 + ks * 4;
    dst[0] = make_uint4(hi[0], hi[4], lo[0], lo[4]);
    dst[1] = make_uint4(hi[1], hi[5], lo[1], lo[5]);
    dst[2] = make_uint4(hi[2], hi[6], lo[2], lo[6]);
    dst[3] = make_uint4(hi[3], hi[7], lo[3], lo[7]);
}

__global__ void __launch_bounds__(256) pack_k_kernel() {
    int idx = blockIdx.x * 256 + threadIdx.x;
    if (idx >= BHN * NPAD * 8) return;
    int ks = idx & 7;
    int tmp = idx >> 3;
    int n = tmp % NPAD;
    int bh = tmp / NPAD;
    float4 ka = make_float4(0.f, 0.f, 0.f, 0.f);
    float4 kb = make_float4(0.f, 0.f, 0.f, 0.f);
    if (n < SEQL) {
        const float* K = g_k + ((size_t)bh * SEQL + n) * HD + 8 * ks;
        ka = *(const float4*)K;
        kb = *(const float4*)(K + 4);
    }
    uint2* dst = g_kp + ((size_t)bh * NT + (n >> 6)) * 2304 + (n & 63) * 36 + ks * 4;
    dst[0] = make_uint2(f2tf32(ka.x), f2tf32(kb.x));
    dst[1] = make_uint2(f2tf32(ka.y), f2tf32(kb.y));
    dst[2] = make_uint2(f2tf32(ka.z), f2tf32(kb.z));
    dst[3] = make_uint2(f2tf32(ka.w), f2tf32(kb.w));
}

__global__ void __launch_bounds__(256) pack_v_kernel() {
    int idx = blockIdx.x * 256 + threadIdx.x;
    if (idx >= BHN * NPAD * 18) return;
    int c4 = idx % 18;
    int tmp = idx / 18;
    int n = tmp % NPAD;
    int bh = tmp / NPAD;
    uint4 val = make_uint4(0u, 0u, 0u, 0u);
    if (c4 < 16 && n < SEQL) {
        float4 v = *(const float4*)(g_v + ((size_t)bh * SEQL + n) * HD + 4 * c4);
        val = make_uint4(f2tf32(v.x), f2tf32(v.y), f2tf32(v.z), f2tf32(v.w));
    }
    *(uint4*)(g_vp + ((size_t)bh * NT + (n >> 6)) * 4608 + (n & 63) * 72 + c4 * 4) = val;
}

// ===================== tensorized GEMM v4: 64-row tiles, 128 thr, K=32 ======
// stage: x 64x36 = 2304 w | W 1280 uint4 = 5120 w ; GBUF2_W = 7424 words
#define GBUF2_W 7424
#define GXW_OFF 2304
#define GEMM_SMEM (2 * GBUF2_W * 4)   // 59392 B

struct GemmAcc { float o[8][4]; };

__device__ __forceinline__ void gemm_issue_v4(
    const float* src, const uint4* wp, int row0, int c2,
    uint32_t sbase, int buf, int tid)
{
    uint32_t base = sbase + (buf ? GBUF2_W * 4 : 0);
#pragma unroll
    for (int u = 0; u < 4; u++) {
        int idx = tid + 128 * u;
        int rr = idx >> 3, c4 = idx & 7;
        int gr = row0 + rr;
        int ok = (gr < ROWS);
        int gc = ok ? gr : (ROWS - 1);
        uint32_t dst = base + (rr * 36 + 4 * c4) * 4;
        const char* s = (const char*)(src + (size_t)gc * EMB + c2 * 32 + 4 * c4);
        CP16Z(dst, s, ok ? 16 : 0);
    }
    const char* ws = (const char*)(wp + (size_t)c2 * 1280);
    uint32_t wd = base + GXW_OFF * 4;
#pragma unroll
    for (int i = 0; i < 10; i++) {
        int off = (tid + 128 * i) * 16;
        CP16(wd + off, ws + off);
    }
}

__device__ __forceinline__ void gemm_core_v4(
    const float* __restrict__ src, const uint4* __restrict__ wp,
    int row0, float* sm, GemmAcc& A)
{
    int tid = threadIdx.x;
    int wid = tid >> 5, lane = tid & 31;
    int g = lane >> 2, tig = lane & 3;
    int wrow = wid * 16;
    uint32_t sbase = smem_to_u32(sm);

    gemm_issue_v4(src, wp, row0, 0, sbase, 0, tid);
    CP_COMMIT();

#pragma unroll
    for (int c2 = 0; c2 < 12; c2++) {
        if (c2 < 11) {
            gemm_issue_v4(src, wp, row0, c2 + 1, sbase, (c2 + 1) & 1, tid);
            CP_COMMIT();
            CP_WAIT1();
        } else {
            CP_WAIT0();
        }
        __syncthreads();

        float* xs = sm + ((c2 & 1) ? GBUF2_W : 0);
        uint4* Wp = (uint4*)(xs + GXW_OFF);
#pragma unroll
        for (int ks = 0; ks < 4; ks++) {
            float a0 = xs[(wrow + g) * 36 + 8 * ks + tig];
            float a1 = xs[(wrow + g + 8) * 36 + 8 * ks + tig];
            float a2 = xs[(wrow + g) * 36 + 8 * ks + tig + 4];
            float a3 = xs[(wrow + g + 8) * 36 + 8 * ks + tig + 4];
            uint32_t ahi[4], alo[4];
            ahi[0] = f2tf32(a0); alo[0] = f2tf32(a0 - __uint_as_float(ahi[0]));
            ahi[1] = f2tf32(a1); alo[1] = f2tf32(a1 - __uint_as_float(ahi[1]));
            ahi[2] = f2tf32(a2); alo[2] = f2tf32(a2 - __uint_as_float(ahi[2]));
            ahi[3] = f2tf32(a3); alo[3] = f2tf32(a3 - __uint_as_float(ahi[3]));
#pragma unroll
            for (int nb = 0; nb < 8; nb++) {
                uint4 w4 = Wp[(nb * 8 + g) * 20 + ks * 4 + tig];
                mma_tf32(A.o[nb], ahi, w4.x, w4.y);
                mma_tf32(A.o[nb], ahi, w4.z, w4.w);
                mma_tf32(A.o[nb], alo, w4.x, w4.y);
            }
        }
        __syncthreads();
    }
}

__global__ void __launch_bounds__(128, 3) qkv_mma_kernel(const float* __restrict__ x)
{
    extern __shared__ float sm[];
    int tid = threadIdx.x;
    int wid = tid >> 5, lane = tid & 31;
    int g = lane >> 2, tig = lane & 3;
    int wrow = wid * 16;
    int rb = blockIdx.x, h = blockIdx.y, z = blockIdx.z;
    int row0 = rb * 64;
    const uint4* wp = g_wp + ((size_t)z * 6 + h) * 12 * 1280;

    GemmAcc A;
#pragma unroll
    for (int nb = 0; nb < 8; nb++)
#pragma unroll
        for (int j = 0; j < 4; j++) A.o[nb][j] = 0.f;

    gemm_core_v4(x, wp, row0, sm, A);

    if (z < 2) {
        float* base = (z == 0) ? g_q : g_k;
#pragma unroll
        for (int nb = 0; nb < 4; nb++)
#pragma unroll
            for (int jj = 0; jj < 4; jj++) {
                int gr = row0 + wrow + g + 8 * (jj >> 1);
                if (gr >= ROWS) continue;
                int b = gr / SEQL, s = gr % SEQL;
                int f = 8 * nb + 2 * tig + (jj & 1);
                float cv = g_cos[(s * HDS + h) * NF + f];
                float sv = g_sin[(s * HDS + h) * NF + f];
                float lov = A.o[nb][jj], hiv = A.o[nb + 4][jj];
                float* dst = base + ((size_t)(b * HDS + h) * SEQL + s) * HD;
                dst[f]      = lov * cv - hiv * sv;
                dst[f + 32] = lov * sv + hiv * cv;
            }
    } else {
#pragma unroll
        for (int nb = 0; nb < 8; nb++)
#pragma unroll
            for (int jj = 0; jj < 4; jj++) {
                int gr = row0 + wrow + g + 8 * (jj >> 1);
                if (gr >= ROWS) continue;
                int b = gr / SEQL, s = gr % SEQL;
                int col = 8 * nb + 2 * tig + (jj & 1);
                g_v[((size_t)(b * HDS + h) * SEQL + s) * HD + col] = A.o[nb][jj];
            }
    }
}

__global__ void __launch_bounds__(128, 3) proj_mma_kernel(
    const float* __restrict__ bo, float* __restrict__ out)
{
    extern __shared__ float sm[];
    int tid = threadIdx.x;
    int wid = tid >> 5, lane = tid & 31;
    int g = lane >> 2, tig = lane & 3;
    int wrow = wid * 16;
    int rb = blockIdx.x, cb = blockIdx.y;
    int row0 = rb * 64, colbase = cb * 64;
    const uint4* wp = g_wp + ((size_t)3 * 6 + cb) * 12 * 1280;

    GemmAcc A;
#pragma unroll
    for (int nb = 0; nb < 8; nb++)
#pragma unroll
        for (int j = 0; j < 4; j++) A.o[nb][j] = 0.f;

    gemm_core_v4(g_ao, wp, row0, sm, A);

#pragma unroll
    for (int nb = 0; nb < 8; nb++)
#pragma unroll
        for (int jj = 0; jj < 4; jj++) {
            int gr = row0 + wrow + g + 8 * (jj >> 1);
            if (gr >= ROWS) continue;
            int col = 8 * nb + 2 * tig + (jj & 1);
            out[(size_t)gr * EMB + colbase + col] = A.o[nb][jj] + bo[colbase + col];
        }
}

// ===================== Flash attention (cp.async pipelined) =================
#define PS_OFF 0
#define KP_OFF 4352
#define V0_OFF 8960
#define V1_OFF 13568
#define ATTN_SMEM (18176 * 4)   // 72704 B

__global__ void __launch_bounds__(128, 3) attn_mma_kernel() {
    extern __shared__ float sm[];
    float* Ps = sm + PS_OFF;
    uint32_t sbase = smem_to_u32(sm);

    int tid = threadIdx.x;
    int wid = tid >> 5, lane = tid & 31;
    int g = lane >> 2, tig = lane & 3;
    int wrow = wid * 16;
    int qb = blockIdx.x, bh = blockIdx.y;

    const float* Q = g_q + (size_t)bh * SEQL * HD;
    const char* gk = (const char*)(g_kp + (size_t)bh * NT * 2304);
    const char* gv = (const char*)(g_vp + (size_t)bh * NT * 4608);

    const uint32_t KPA = sbase + KP_OFF * 4;
    const uint32_t VA[2] = { sbase + V0_OFF * 4, sbase + V1_OFF * 4 };

#pragma unroll
    for (int i = 0; i < 9; i++) {
        int off = (tid + 128 * i) * 16;
        CP16(KPA + off, gk + off);
        CP16(VA[0] + off, gv + off);
    }
    CP_COMMIT();

#pragma unroll
    for (int u = 0; u < 8; u++) {
        int idx = tid + 128 * u;
        int rr = idx >> 4, c4 = idx & 15;
        int s = qb * 64 + rr;
        float4 v = make_float4(0.f, 0.f, 0.f, 0.f);
        if (s < SEQL) v = *(const float4*)(Q + (size_t)s * HD + c4 * 4);
        v.x *= 0.125f; v.y *= 0.125f; v.z *= 0.125f; v.w *= 0.125f;
        *(float4*)(Ps + rr * 68 + c4 * 4) = v;
    }
    __syncthreads();

    uint32_t qhi[8][4];
#pragma unroll
    for (int ks = 0; ks < 8; ks++) {
#pragma unroll
        for (int j = 0; j < 4; j++) {
            int rr = wrow + g + (j & 1) * 8;
            int cc = 8 * ks + tig + (j >> 1) * 4;
            qhi[ks][j] = f2tf32(Ps[rr * 68 + cc]);
        }
    }

    float o[8][4] = {};
    float m0 = -INFINITY, m1 = -INFINITY, l0 = 0.f, l1 = 0.f;

    for (int t = 0; t < NT; t++) {
        CP_WAIT0();
        __syncthreads();

        if (t < NT - 1) {
            const char* vsrc = gv + (size_t)(t + 1) * 4608 * 4;
            uint32_t vdst = VA[(t + 1) & 1];
#pragma unroll
            for (int i = 0; i < 9; i++) {
                int off = (tid + 128 * i) * 16;
                CP16(vdst + off, vsrc + off);
            }
            CP_COMMIT();
        }

        uint2* Kp = (uint2*)(sm + KP_OFF);
        float s_[8][4] = {};
#pragma unroll
        for (int ks = 0; ks < 8; ks++) {
#pragma unroll
            for (int nb = 0; nb < 8; nb++) {
                uint2 kk = Kp[(nb * 8 + g) * 36 + ks * 4 + tig];
                mma_tf32(s_[nb], qhi[ks], kk.x, kk.y);
            }
        }
        __syncthreads();

        if (t < NT - 1) {
            const char* ksrc = gk + (size_t)(t + 1) * 2304 * 8;
#pragma unroll
            for (int i = 0; i < 9; i++) {
                int off = (tid + 128 * i) * 16;
                CP16(KPA + off, ksrc + off);
            }
            CP_COMMIT();
        }

        if (t == NT - 1) {
#pragma unroll
            for (int nb = 0; nb < 8; nb++) {
                int c = 1024 + nb * 8 + 2 * tig;
                if (c >= SEQL)     { s_[nb][0] = -INFINITY; s_[nb][2] = -INFINITY; }
                if (c + 1 >= SEQL) { s_[nb][1] = -INFINITY; s_[nb][3] = -INFINITY; }
            }
        }

        float rm0 = -INFINITY, rm1 = -INFINITY;
#pragma unroll
        for (int nb = 0; nb < 8; nb++) {
            rm0 = fmaxf(rm0, fmaxf(s_[nb][0], s_[nb][1]));
            rm1 = fmaxf(rm1, fmaxf(s_[nb][2], s_[nb][3]));
        }
        rm0 = fmaxf(rm0, __shfl_xor_sync(0xffffffffu, rm0, 1));
        rm0 = fmaxf(rm0, __shfl_xor_sync(0xffffffffu, rm0, 2));
        rm1 = fmaxf(rm1, __shfl_xor_sync(0xffffffffu, rm1, 1));
        rm1 = fmaxf(rm1, __shfl_xor_sync(0xffffffffu, rm1, 2));
        float nm0 = fmaxf(m0, rm0), nm1 = fmaxf(m1, rm1);
        float corr0 = __expf(m0 - nm0), corr1 = __expf(m1 - nm1);
        m0 = nm0; m1 = nm1;

        float rs0 = 0.f, rs1 = 0.f;
#pragma unroll
        for (int nb = 0; nb < 8; nb++) {
            s_[nb][0] = __expf(s_[nb][0] - m0);
            s_[nb][1] = __expf(s_[nb][1] - m0);
            s_[nb][2] = __expf(s_[nb][2] - m1);
            s_[nb][3] = __expf(s_[nb][3] - m1);
            rs0 += s_[nb][0] + s_[nb][1];
            rs1 += s_[nb][2] + s_[nb][3];
        }
        rs0 += __shfl_xor_sync(0xffffffffu, rs0, 1);
        rs0 += __shfl_xor_sync(0xffffffffu, rs0, 2);
        rs1 += __shfl_xor_sync(0xffffffffu, rs1, 1);
        rs1 += __shfl_xor_sync(0xffffffffu, rs1, 2);
        l0 = l0 * corr0 + rs0;
        l1 = l1 * corr1 + rs1;

#pragma unroll
        for (int nb = 0; nb < 8; nb++) {
            o[nb][0] *= corr0; o[nb][1] *= corr0;
            o[nb][2] *= corr1; o[nb][3] *= corr1;
        }

#pragma unroll
        for (int nb = 0; nb < 8; nb++) {
            *(float2*)(Ps + (wrow + g) * 68 + nb * 8 + 2 * tig)     = make_float2(s_[nb][0], s_[nb][1]);
            *(float2*)(Ps + (wrow + g + 8) * 68 + nb * 8 + 2 * tig) = make_float2(s_[nb][2], s_[nb][3]);
        }
        __syncwarp();

        uint32_t* Vs = (uint32_t*)(sm + ((t & 1) ? V1_OFF : V0_OFF));
#pragma unroll
        for (int ks = 0; ks < 8; ks++) {
            uint32_t pa[4];
            pa[0] = f2tf32(Ps[(wrow + g) * 68 + 8 * ks + tig]);
            pa[1] = f2tf32(Ps[(wrow + g + 8) * 68 + 8 * ks + tig]);
            pa[2] = f2tf32(Ps[(wrow + g) * 68 + 8 * ks + tig + 4]);
            pa[3] = f2tf32(Ps[(wrow + g + 8) * 68 + 8 * ks + tig + 4]);
#pragma unroll
            for (int nb = 0; nb < 8; nb++) {
                int r0 = 8 * ks + tig;
                int cc = nb * 8 + g;
                mma_tf32(o[nb], pa, Vs[r0 * 72 + cc], Vs[(r0 + 4) * 72 + cc]);
            }
        }
    }

    float inv0 = 1.0f / l0, inv1 = 1.0f / l1;
    int b = bh / HDS, h = bh % HDS;
    int s0 = qb * 64 + wrow + g;
    int s1 = s0 + 8;
#pragma unroll
    for (int nb = 0; nb < 8; nb++) {
        int cc = nb * 8 + 2 * tig;
        if (s0 < SEQL) {
            float* dst = g_ao + ((size_t)b * SEQL + s0) * EMB + h * HD + cc;
            *(float2*)dst = make_float2(o[nb][0] * inv0, o[nb][1] * inv0);
        }
        if (s1 < SEQL) {
            float* dst = g_ao + ((size_t)b * SEQL + s1) * EMB + h * HD + cc;
            *(float2*)dst = make_float2(o[nb][2] * inv1, o[nb][3] * inv1);
        }
    }
}

// ===================== launch =====================
extern "C" void kernel_launch(void* const* d_in, const int* in_sizes, int n_in,
                              void* d_out, int out_size)
{
    const float* x  = (const float*)d_in[0];
    const float* Wq = (const float*)d_in[1];
    const float* Wk = (const float*)d_in[2];
    const float* Wv = (const float*)d_in[3];
    const float* Wo = (const float*)d_in[4];
    const float* bo = (const float*)d_in[5];
    float* out = (float*)d_out;

    double xg = 2.0;
    for (int it = 0; it < 10; ++it) xg = pow(1.0 + xg, 1.0 / 3.0);
    float inv_g = (float)(1.0 / xg);

    cudaFuncSetAttribute(attn_mma_kernel,
                         cudaFuncAttributeMaxDynamicSharedMemorySize, ATTN_SMEM);
    cudaFuncSetAttribute(qkv_mma_kernel,
                         cudaFuncAttributeMaxDynamicSharedMemorySize, GEMM_SMEM);
    cudaFuncSetAttribute(proj_mma_kernel,
                         cudaFuncAttributeMaxDynamicSharedMemorySize, GEMM_SMEM);

    init_freqs<<<1, 192>>>(inv_g);
    init_trig<<<(SEQL * HDS * NF + 255) / 256, 256>>>();
    pack_w_kernel<<<(4 * 72 * 256 + 255) / 256, 256>>>(Wq, Wk, Wv, Wo);

    dim3 qkv_grid((ROWS + 63) / 64, HDS, 3);
    qkv_mma_kernel<<<qkv_grid, 128, GEMM_SMEM>>>(x);

    pack_k_kernel<<<(BHN * NPAD * 8 + 255) / 256, 256>>>();
    pack_v_kernel<<<(BHN * NPAD * 18 + 255) / 256, 256>>>();

    dim3 attn_grid(NT, BHN);
    attn_mma_kernel<<<attn_grid, 128, ATTN_SMEM>>>();

    dim3 proj_grid((ROWS + 63) / 64, EMB / 64);
    proj_mma_kernel<<<proj_grid, 128, GEMM_SMEM>>>(bo, out);
}

// round 13
// speedup vs baseline: 1.2967x; 1.0752x over previous
#include <cuda_runtime.h>
#include <math.h>
#include <stdint.h>

#define BB 16
#define SEQL 1025
#define EMB 384
#define HDS 6
#define HD 64
#define NF 32
#define ROWS (BB*SEQL)
#define BHN (BB*HDS)
#define NT 17
#define NPAD (NT*64)

__device__ float g_q[(size_t)BHN*SEQL*HD];
__device__ float g_k[(size_t)BHN*SEQL*HD];
__device__ float g_v[(size_t)BHN*SEQL*HD];
__device__ float g_ao[(size_t)ROWS*EMB];
__device__ float g_cos[SEQL*HDS*NF];
__device__ float g_sin[SEQL*HDS*NF];
__device__ float g_freqs[HDS*NF*2];
__device__ uint2    g_kp[(size_t)BHN*NT*2304];
__device__ uint32_t g_vp[(size_t)BHN*NT*4608];
// packed W, K=32 chunks: [mat*72 + cb*12 + c2] x (64 n x 20 uint4)
__device__ uint4    g_wp[(size_t)4*6*12*1280];

// ===================== mma.sync helpers =====================
__device__ __forceinline__ uint32_t f2tf32(float x) {
    uint32_t r;
    asm("cvt.rna.tf32.f32 %0, %1;" : "=r"(r) : "f"(x));
    return r;
}
__device__ __forceinline__ void mma_tf32(float* d, const uint32_t* a,
                                         uint32_t b0, uint32_t b1) {
    asm volatile(
        "mma.sync.aligned.m16n8k8.row.col.f32.tf32.tf32.f32 "
        "{%0,%1,%2,%3}, {%4,%5,%6,%7}, {%8,%9}, {%0,%1,%2,%3};"
        : "+f"(d[0]), "+f"(d[1]), "+f"(d[2]), "+f"(d[3])
        : "r"(a[0]), "r"(a[1]), "r"(a[2]), "r"(a[3]), "r"(b0), "r"(b1));
}
__device__ __forceinline__ uint32_t smem_to_u32(const void* p) {
    uint32_t a;
    asm("{ .reg .u64 t; cvta.to.shared.u64 t, %1; cvt.u32.u64 %0, t; }" : "=r"(a) : "l"(p));
    return a;
}
#define CP16(dst, src) \
    asm volatile("cp.async.cg.shared.global [%0], [%1], 16;" :: "r"(dst), "l"(src))
#define CP16Z(dst, src, sz) \
    asm volatile("cp.async.cg.shared.global [%0], [%1], 16, %2;" :: "r"(dst), "l"(src), "r"(sz))
#define CP_COMMIT() asm volatile("cp.async.commit_group;" ::: "memory")
#define CP_WAIT0()  asm volatile("cp.async.wait_group 0;" ::: "memory")
#define CP_WAIT1()  asm volatile("cp.async.wait_group 1;" ::: "memory")

// ===================== init (bit-matched constants) =====================
__device__ __forceinline__ float erfinv_xla(float x) {
    float w = -log1pf(-__fmul_rn(x, x));
    float p;
    if (w < 5.0f) {
        w = w - 2.5f;
        p = 2.81022636e-08f;
        p = fmaf(p, w, 3.43273939e-07f);
        p = fmaf(p, w, -3.5233877e-06f);
        p = fmaf(p, w, -4.39150654e-06f);
        p = fmaf(p, w, 0.00021858087f);
        p = fmaf(p, w, -0.00125372503f);
        p = fmaf(p, w, -0.00417768164f);
        p = fmaf(p, w, 0.246640727f);
        p = fmaf(p, w, 1.50140941f);
    } else {
        w = sqrtf(w) - 3.0f;
        p = -0.000200214257f;
        p = fmaf(p, w, 0.000100950558f);
        p = fmaf(p, w, 0.00134934322f);
        p = fmaf(p, w, -0.00367342844f);
        p = fmaf(p, w, 0.00573950773f);
        p = fmaf(p, w, -0.0076224613f);
        p = fmaf(p, w, 0.00943887047f);
        p = fmaf(p, w, 1.00167406f);
        p = fmaf(p, w, 2.83297682f);
    }
    return p * x;
}

__global__ void init_freqs(float inv_g) {
    int n = threadIdx.x;
    if (n >= HDS * NF) return;
    float alpha0 = powf(inv_g, 1.0f);
    float alpha1 = powf(inv_g, 2.0f);
    float fi = (float)(n + 1);
    float z0 = fmodf(__fmul_rn(fi, alpha0), 1.0f);
    float z1 = fmodf(__fmul_rn(fi, alpha1), 1.0f);
    float d0 = erfinv_xla(__fmul_rn(2.0f, z0) - 1.0f);
    float d1 = erfinv_xla(__fmul_rn(2.0f, z1) - 1.0f);
    float nrm = sqrtf(__fadd_rn(__fmul_rn(d0, d0), __fmul_rn(d1, d1)));
    d0 = __fdiv_rn(d0, nrm);
    d1 = __fdiv_rn(d1, nrm);
    int f = n % NF;
    float t = __fmul_rn((float)f, (1.0f / 31.0f));
    float omega = __fmul_rn(0.1f, powf(10000.0f, t));
    g_freqs[n * 2 + 0] = __fmul_rn(d0, omega);
    g_freqs[n * 2 + 1] = __fmul_rn(d1, omega);
}

__global__ void init_trig() {
    int idx = blockIdx.x * blockDim.x + threadIdx.x;
    if (idx >= SEQL * HDS * NF) return;
    int s = idx / (HDS * NF);
    int r = idx % (HDS * NF);
    float c0 = 0.f, c1 = 0.f;
    if (s > 0) {
        int p = s - 1;
        int xi = p % 32, yi = p / 32;
        c0 = __fmul_rn(__fdiv_rn((float)xi, 31.0f), 2.0f) - 1.0f;
        c1 = __fmul_rn(__fdiv_rn((float)yi, 31.0f), 2.0f) - 1.0f;
    }
    float th = __fadd_rn(__fmul_rn(g_freqs[r * 2 + 0], c0), __fmul_rn(g_freqs[r * 2 + 1], c1));
    g_cos[idx] = cosf(th);
    g_sin[idx] = sinf(th);
}

// ===================== one-shot pack kernels =====================
__global__ void __launch_bounds__(256) pack_w_kernel(
    const float* __restrict__ Wq, const float* __restrict__ Wk,
    const float* __restrict__ Wv, const float* __restrict__ Wo)
{
    int idx = blockIdx.x * 256 + threadIdx.x;
    if (idx >= 4 * 72 * 256) return;
    int ks = idx & 3;
    int n = (idx >> 2) & 63;
    int r2 = idx >> 8;
    int mat = r2 / 72;
    int rem = r2 % 72;
    int cb = rem / 12, c2 = rem % 12;
    const float* W = (mat == 0) ? Wq : (mat == 1) ? Wk : (mat == 2) ? Wv : Wo;
    int colbase = cb * 64, k0 = c2 * 32;
    float wv[8];
#pragma unroll
    for (int j = 0; j < 8; j++)
        wv[j] = W[(size_t)(k0 + 8 * ks + j) * EMB + colbase + n];
    uint32_t hi[8], lo[8];
#pragma unroll
    for (int j = 0; j < 8; j++) {
        hi[j] = f2tf32(wv[j]);
        lo[j] = f2tf32(wv[j] - __uint_as_float(hi[j]));
    }
    uint4* dst = g_wp + (size_t)r2 * 1280 + n * 20 + ks * 4;
    dst[0] = make_uint4(hi[0], hi[4], lo[0], lo[4]);
    dst[1] = make_uint4(hi[1], hi[5], lo[1], lo[5]);
    dst[2] = make_uint4(hi[2], hi[6], lo[2], lo[6]);
    dst[3] = make_uint4(hi[3], hi[7], lo[3], lo[7]);
}

__global__ void __launch_bounds__(256) pack_k_kernel() {
    int idx = blockIdx.x * 256 + threadIdx.x;
    if (idx >= BHN * NPAD * 8) return;
    int ks = idx & 7;
    int tmp = idx >> 3;
    int n = tmp % NPAD;
    int bh = tmp / NPAD;
    float4 ka = make_float4(0.f, 0.f, 0.f, 0.f);
    float4 kb = make_float4(0.f, 0.f, 0.f, 0.f);
    if (n < SEQL) {
        const float* K = g_k + ((size_t)bh * SEQL + n) * HD + 8 * ks;
        ka = *(const float4*)K;
        kb = *(const float4*)(K + 4);
    }
    uint2* dst = g_kp + ((size_t)bh * NT + (n >> 6)) * 2304 + (n & 63) * 36 + ks * 4;
    dst[0] = make_uint2(f2tf32(ka.x), f2tf32(kb.x));
    dst[1] = make_uint2(f2tf32(ka.y), f2tf32(kb.y));
    dst[2] = make_uint2(f2tf32(ka.z), f2tf32(kb.z));
    dst[3] = make_uint2(f2tf32(ka.w), f2tf32(kb.w));
}

__global__ void __launch_bounds__(256) pack_v_kernel() {
    int idx = blockIdx.x * 256 + threadIdx.x;
    if (idx >= BHN * NPAD * 18) return;
    int c4 = idx % 18;
    int tmp = idx / 18;
    int n = tmp % NPAD;
    int bh = tmp / NPAD;
    uint4 val = make_uint4(0u, 0u, 0u, 0u);
    if (c4 < 16 && n < SEQL) {
        float4 v = *(const float4*)(g_v + ((size_t)bh * SEQL + n) * HD + 4 * c4);
        val = make_uint4(f2tf32(v.x), f2tf32(v.y), f2tf32(v.z), f2tf32(v.w));
    }
    *(uint4*)(g_vp + ((size_t)bh * NT + (n >> 6)) * 4608 + (n & 63) * 72 + c4 * 4) = val;
}

// ===================== tensorized GEMM v5: 2-pass (x tf32, W hi/lo) =========
#define GBUF2_W 7424
#define GXW_OFF 2304
#define GEMM_SMEM (2 * GBUF2_W * 4)   // 59392 B

struct GemmAcc { float o[8][4]; };

__device__ __forceinline__ void gemm_issue_v4(
    const float* src, const uint4* wp, int row0, int c2,
    uint32_t sbase, int buf, int tid)
{
    uint32_t base = sbase + (buf ? GBUF2_W * 4 : 0);
#pragma unroll
    for (int u = 0; u < 4; u++) {
        int idx = tid + 128 * u;
        int rr = idx >> 3, c4 = idx & 7;
        int gr = row0 + rr;
        int ok = (gr < ROWS);
        int gc = ok ? gr : (ROWS - 1);
        uint32_t dst = base + (rr * 36 + 4 * c4) * 4;
        const char* s = (const char*)(src + (size_t)gc * EMB + c2 * 32 + 4 * c4);
        CP16Z(dst, s, ok ? 16 : 0);
    }
    const char* ws = (const char*)(wp + (size_t)c2 * 1280);
    uint32_t wd = base + GXW_OFF * 4;
#pragma unroll
    for (int i = 0; i < 10; i++) {
        int off = (tid + 128 * i) * 16;
        CP16(wd + off, ws + off);
    }
}

__device__ __forceinline__ void gemm_core_v5(
    const float* __restrict__ src, const uint4* __restrict__ wp,
    int row0, float* sm, GemmAcc& A)
{
    int tid = threadIdx.x;
    int wid = tid >> 5, lane = tid & 31;
    int g = lane >> 2, tig = lane & 3;
    int wrow = wid * 16;
    uint32_t sbase = smem_to_u32(sm);

    gemm_issue_v4(src, wp, row0, 0, sbase, 0, tid);
    CP_COMMIT();

#pragma unroll
    for (int c2 = 0; c2 < 12; c2++) {
        if (c2 < 11) {
            gemm_issue_v4(src, wp, row0, c2 + 1, sbase, (c2 + 1) & 1, tid);
            CP_COMMIT();
            CP_WAIT1();
        } else {
            CP_WAIT0();
        }
        __syncthreads();

        float* xs = sm + ((c2 & 1) ? GBUF2_W : 0);
        uint4* Wp = (uint4*)(xs + GXW_OFF);
#pragma unroll
        for (int ks = 0; ks < 4; ks++) {
            uint32_t ahi[4];
            ahi[0] = f2tf32(xs[(wrow + g) * 36 + 8 * ks + tig]);
            ahi[1] = f2tf32(xs[(wrow + g + 8) * 36 + 8 * ks + tig]);
            ahi[2] = f2tf32(xs[(wrow + g) * 36 + 8 * ks + tig + 4]);
            ahi[3] = f2tf32(xs[(wrow + g + 8) * 36 + 8 * ks + tig + 4]);
#pragma unroll
            for (int nb = 0; nb < 8; nb++) {
                uint4 w4 = Wp[(nb * 8 + g) * 20 + ks * 4 + tig];
                mma_tf32(A.o[nb], ahi, w4.x, w4.y);
                mma_tf32(A.o[nb], ahi, w4.z, w4.w);
            }
        }
        __syncthreads();
    }
}

__global__ void __launch_bounds__(128, 3) qkv_mma_kernel(const float* __restrict__ x)
{
    extern __shared__ float sm[];
    int tid = threadIdx.x;
    int wid = tid >> 5, lane = tid & 31;
    int g = lane >> 2, tig = lane & 3;
    int wrow = wid * 16;
    int rb = blockIdx.x, h = blockIdx.y, z = blockIdx.z;
    int row0 = rb * 64;
    const uint4* wp = g_wp + ((size_t)z * 6 + h) * 12 * 1280;

    GemmAcc A;
#pragma unroll
    for (int nb = 0; nb < 8; nb++)
#pragma unroll
        for (int j = 0; j < 4; j++) A.o[nb][j] = 0.f;

    gemm_core_v5(x, wp, row0, sm, A);

    if (z < 2) {
        float* base = (z == 0) ? g_q : g_k;
#pragma unroll
        for (int nb = 0; nb < 4; nb++)
#pragma unroll
            for (int jj = 0; jj < 4; jj++) {
                int gr = row0 + wrow + g + 8 * (jj >> 1);
                if (gr >= ROWS) continue;
                int b = gr / SEQL, s = gr % SEQL;
                int f = 8 * nb + 2 * tig + (jj & 1);
                float cv = g_cos[(s * HDS + h) * NF + f];
                float sv = g_sin[(s * HDS + h) * NF + f];
                float lov = A.o[nb][jj], hiv = A.o[nb + 4][jj];
                float* dst = base + ((size_t)(b * HDS + h) * SEQL + s) * HD;
                dst[f]      = lov * cv - hiv * sv;
                dst[f + 32] = lov * sv + hiv * cv;
            }
    } else {
#pragma unroll
        for (int nb = 0; nb < 8; nb++)
#pragma unroll
            for (int jj = 0; jj < 4; jj++) {
                int gr = row0 + wrow + g + 8 * (jj >> 1);
                if (gr >= ROWS) continue;
                int b = gr / SEQL, s = gr % SEQL;
                int col = 8 * nb + 2 * tig + (jj & 1);
                g_v[((size_t)(b * HDS + h) * SEQL + s) * HD + col] = A.o[nb][jj];
            }
    }
}

__global__ void __launch_bounds__(128, 3) proj_mma_kernel(
    const float* __restrict__ bo, float* __restrict__ out)
{
    extern __shared__ float sm[];
    int tid = threadIdx.x;
    int wid = tid >> 5, lane = tid & 31;
    int g = lane >> 2, tig = lane & 3;
    int wrow = wid * 16;
    int rb = blockIdx.x, cb = blockIdx.y;
    int row0 = rb * 64, colbase = cb * 64;
    const uint4* wp = g_wp + ((size_t)3 * 6 + cb) * 12 * 1280;

    GemmAcc A;
#pragma unroll
    for (int nb = 0; nb < 8; nb++)
#pragma unroll
        for (int j = 0; j < 4; j++) A.o[nb][j] = 0.f;

    gemm_core_v5(g_ao, wp, row0, sm, A);

#pragma unroll
    for (int nb = 0; nb < 8; nb++)
#pragma unroll
        for (int jj = 0; jj < 4; jj++) {
            int gr = row0 + wrow + g + 8 * (jj >> 1);
            if (gr >= ROWS) continue;
            int col = 8 * nb + 2 * tig + (jj & 1);
            out[(size_t)gr * EMB + colbase + col] = A.o[nb][jj] + bo[colbase + col];
        }
}

// ===================== Flash attention (cp.async pipelined) =================
#define PS_OFF 0
#define KP_OFF 4352
#define V0_OFF 8960
#define V1_OFF 13568
#define ATTN_SMEM (18176 * 4)   // 72704 B

__global__ void __launch_bounds__(128, 3) attn_mma_kernel() {
    extern __shared__ float sm[];
    float* Ps = sm + PS_OFF;
    uint32_t sbase = smem_to_u32(sm);

    int tid = threadIdx.x;
    int wid = tid >> 5, lane = tid & 31;
    int g = lane >> 2, tig = lane & 3;
    int wrow = wid * 16;
    int qb = blockIdx.x, bh = blockIdx.y;

    const float* Q = g_q + (size_t)bh * SEQL * HD;
    const char* gk = (const char*)(g_kp + (size_t)bh * NT * 2304);
    const char* gv = (const char*)(g_vp + (size_t)bh * NT * 4608);

    const uint32_t KPA = sbase + KP_OFF * 4;
    const uint32_t VA[2] = { sbase + V0_OFF * 4, sbase + V1_OFF * 4 };

#pragma unroll
    for (int i = 0; i < 9; i++) {
        int off = (tid + 128 * i) * 16;
        CP16(KPA + off, gk + off);
        CP16(VA[0] + off, gv + off);
    }
    CP_COMMIT();

#pragma unroll
    for (int u = 0; u < 8; u++) {
        int idx = tid + 128 * u;
        int rr = idx >> 4, c4 = idx & 15;
        int s = qb * 64 + rr;
        float4 v = make_float4(0.f, 0.f, 0.f, 0.f);
        if (s < SEQL) v = *(const float4*)(Q + (size_t)s * HD + c4 * 4);
        v.x *= 0.125f; v.y *= 0.125f; v.z *= 0.125f; v.w *= 0.125f;
        *(float4*)(Ps + rr * 68 + c4 * 4) = v;
    }
    __syncthreads();

    uint32_t qhi[8][4];
#pragma unroll
    for (int ks = 0; ks < 8; ks++) {
#pragma unroll
        for (int j = 0; j < 4; j++) {
            int rr = wrow + g + (j & 1) * 8;
            int cc = 8 * ks + tig + (j >> 1) * 4;
            qhi[ks][j] = f2tf32(Ps[rr * 68 + cc]);
        }
    }

    float o[8][4] = {};
    float m0 = -INFINITY, m1 = -INFINITY, l0 = 0.f, l1 = 0.f;

    for (int t = 0; t < NT; t++) {
        CP_WAIT0();
        __syncthreads();

        if (t < NT - 1) {
            const char* vsrc = gv + (size_t)(t + 1) * 4608 * 4;
            uint32_t vdst = VA[(t + 1) & 1];
#pragma unroll
            for (int i = 0; i < 9; i++) {
                int off = (tid + 128 * i) * 16;
                CP16(vdst + off, vsrc + off);
            }
            CP_COMMIT();
        }

        uint2* Kp = (uint2*)(sm + KP_OFF);
        float s_[8][4] = {};
#pragma unroll
        for (int ks = 0; ks < 8; ks++) {
#pragma unroll
            for (int nb = 0; nb < 8; nb++) {
                uint2 kk = Kp[(nb * 8 + g) * 36 + ks * 4 + tig];
                mma_tf32(s_[nb], qhi[ks], kk.x, kk.y);
            }
        }
        __syncthreads();

        if (t < NT - 1) {
            const char* ksrc = gk + (size_t)(t + 1) * 2304 * 8;
#pragma unroll
            for (int i = 0; i < 9; i++) {
                int off = (tid + 128 * i) * 16;
                CP16(KPA + off, ksrc + off);
            }
            CP_COMMIT();
        }

        if (t == NT - 1) {
#pragma unroll
            for (int nb = 0; nb < 8; nb++) {
                int c = 1024 + nb * 8 + 2 * tig;
                if (c >= SEQL)     { s_[nb][0] = -INFINITY; s_[nb][2] = -INFINITY; }
                if (c + 1 >= SEQL) { s_[nb][1] = -INFINITY; s_[nb][3] = -INFINITY; }
            }
        }

        float rm0 = -INFINITY, rm1 = -INFINITY;
#pragma unroll
        for (int nb = 0; nb < 8; nb++) {
            rm0 = fmaxf(rm0, fmaxf(s_[nb][0], s_[nb][1]));
            rm1 = fmaxf(rm1, fmaxf(s_[nb][2], s_[nb][3]));
        }
        rm0 = fmaxf(rm0, __shfl_xor_sync(0xffffffffu, rm0, 1));
        rm0 = fmaxf(rm0, __shfl_xor_sync(0xffffffffu, rm0, 2));
        rm1 = fmaxf(rm1, __shfl_xor_sync(0xffffffffu, rm1, 1));
        rm1 = fmaxf(rm1, __shfl_xor_sync(0xffffffffu, rm1, 2));
        float nm0 = fmaxf(m0, rm0), nm1 = fmaxf(m1, rm1);
        float corr0 = __expf(m0 - nm0), corr1 = __expf(m1 - nm1);
        m0 = nm0; m1 = nm1;

        float rs0 = 0.f, rs1 = 0.f;
#pragma unroll
        for (int nb = 0; nb < 8; nb++) {
            s_[nb][0] = __expf(s_[nb][0] - m0);
            s_[nb][1] = __expf(s_[nb][1] - m0);
            s_[nb][2] = __expf(s_[nb][2] - m1);
            s_[nb][3] = __expf(s_[nb][3] - m1);
            rs0 += s_[nb][0] + s_[nb][1];
            rs1 += s_[nb][2] + s_[nb][3];
        }
        rs0 += __shfl_xor_sync(0xffffffffu, rs0, 1);
        rs0 += __shfl_xor_sync(0xffffffffu, rs0, 2);
        rs1 += __shfl_xor_sync(0xffffffffu, rs1, 1);
        rs1 += __shfl_xor_sync(0xffffffffu, rs1, 2);
        l0 = l0 * corr0 + rs0;
        l1 = l1 * corr1 + rs1;

#pragma unroll
        for (int nb = 0; nb < 8; nb++) {
            o[nb][0] *= corr0; o[nb][1] *= corr0;
            o[nb][2] *= corr1; o[nb][3] *= corr1;
        }

#pragma unroll
        for (int nb = 0; nb < 8; nb++) {
            *(float2*)(Ps + (wrow + g) * 68 + nb * 8 + 2 * tig)     = make_float2(s_[nb][0], s_[nb][1]);
            *(float2*)(Ps + (wrow + g + 8) * 68 + nb * 8 + 2 * tig) = make_float2(s_[nb][2], s_[nb][3]);
        }
        __syncwarp();

        uint32_t* Vs = (uint32_t*)(sm + ((t & 1) ? V1_OFF : V0_OFF));
#pragma unroll
        for (int ks = 0; ks < 8; ks++) {
            uint32_t pa[4];
            pa[0] = f2tf32(Ps[(wrow + g) * 68 + 8 * ks + tig]);
            pa[1] = f2tf32(Ps[(wrow + g + 8) * 68 + 8 * ks + tig]);
            pa[2] = f2tf32(Ps[(wrow + g) * 68 + 8 * ks + tig + 4]);
            pa[3] = f2tf32(Ps[(wrow + g + 8) * 68 + 8 * ks + tig + 4]);
#pragma unroll
            for (int nb = 0; nb < 8; nb++) {
                int r0 = 8 * ks + tig;
                int cc = nb * 8 + g;
                mma_tf32(o[nb], pa, Vs[r0 * 72 + cc], Vs[(r0 + 4) * 72 + cc]);
            }
        }
    }

    float inv0 = 1.0f / l0, inv1 = 1.0f / l1;
    int b = bh / HDS, h = bh % HDS;
    int s0 = qb * 64 + wrow + g;
    int s1 = s0 + 8;
#pragma unroll
    for (int nb = 0; nb < 8; nb++) {
        int cc = nb * 8 + 2 * tig;
        if (s0 < SEQL) {
            float* dst = g_ao + ((size_t)b * SEQL + s0) * EMB + h * HD + cc;
            *(float2*)dst = make_float2(o[nb][0] * inv0, o[nb][1] * inv0);
        }
        if (s1 < SEQL) {
            float* dst = g_ao + ((size_t)b * SEQL + s1) * EMB + h * HD + cc;
            *(float2*)dst = make_float2(o[nb][2] * inv1, o[nb][3] * inv1);
        }
    }
}

// ===================== launch =====================
extern "C" void kernel_launch(void* const* d_in, const int* in_sizes, int n_in,
                              void* d_out, int out_size)
{
    const float* x  = (const float*)d_in[0];
    const float* Wq = (const float*)d_in[1];
    const float* Wk = (const float*)d_in[2];
    const float* Wv = (const float*)d_in[3];
    const float* Wo = (const float*)d_in[4];
    const float* bo = (const float*)d_in[5];
    float* out = (float*)d_out;

    double xg = 2.0;
    for (int it = 0; it < 10; ++it) xg = pow(1.0 + xg, 1.0 / 3.0);
    float inv_g = (float)(1.0 / xg);

    cudaFuncSetAttribute(attn_mma_kernel,
                         cudaFuncAttributeMaxDynamicSharedMemorySize, ATTN_SMEM);
    cudaFuncSetAttribute(qkv_mma_kernel,
                         cudaFuncAttributeMaxDynamicSharedMemorySize, GEMM_SMEM);
    cudaFuncSetAttribute(proj_mma_kernel,
                         cudaFuncAttributeMaxDynamicSharedMemorySize, GEMM_SMEM);

    init_freqs<<<1, 192>>>(inv_g);
    init_trig<<<(SEQL * HDS * NF + 255) / 256, 256>>>();
    pack_w_kernel<<<(4 * 72 * 256 + 255) / 256, 256>>>(Wq, Wk, Wv, Wo);

    dim3 qkv_grid((ROWS + 63) / 64, HDS, 3);
    qkv_mma_kernel<<<qkv_grid, 128, GEMM_SMEM>>>(x);

    pack_k_kernel<<<(BHN * NPAD * 8 + 255) / 256, 256>>>();
    pack_v_kernel<<<(BHN * NPAD * 18 + 255) / 256, 256>>>();

    dim3 attn_grid(NT, BHN);
    attn_mma_kernel<<<attn_grid, 128, ATTN_SMEM>>>();

    dim3 proj_grid((ROWS + 63) / 64, EMB / 64);
    proj_mma_kernel<<<proj_grid, 128, GEMM_SMEM>>>(bo, out);
}

// round 14
// speedup vs baseline: 1.3786x; 1.0632x over previous
#include <cuda_runtime.h>
#include <math.h>
#include <stdint.h>

#define BB 16
#define SEQL 1025
#define EMB 384
#define HDS 6
#define HD 64
#define NF 32
#define ROWS (BB*SEQL)
#define BHN (BB*HDS)
#define NT 17
#define NPAD (NT*64)

__device__ float g_q[(size_t)BHN*SEQL*HD];
__device__ float g_ao[(size_t)ROWS*EMB];
__device__ float g_cos[SEQL*HDS*NF];
__device__ float g_sin[SEQL*HDS*NF];
__device__ float g_freqs[HDS*NF*2];
// packed K fragments (zero-init covers pad rows; never overwritten there)
__device__ uint2    g_kp[(size_t)BHN*NT*2304];
// padded tf32 V (zero-init covers pad rows)
__device__ uint32_t g_vp[(size_t)BHN*NT*4608];
// packed weights, K=32 chunks
__device__ uint4    g_wp[(size_t)4*6*12*1280];

// ===================== mma.sync helpers =====================
__device__ __forceinline__ uint32_t f2tf32(float x) {
    uint32_t r;
    asm("cvt.rna.tf32.f32 %0, %1;" : "=r"(r) : "f"(x));
    return r;
}
__device__ __forceinline__ void mma_tf32(float* d, const uint32_t* a,
                                         uint32_t b0, uint32_t b1) {
    asm volatile(
        "mma.sync.aligned.m16n8k8.row.col.f32.tf32.tf32.f32 "
        "{%0,%1,%2,%3}, {%4,%5,%6,%7}, {%8,%9}, {%0,%1,%2,%3};"
        : "+f"(d[0]), "+f"(d[1]), "+f"(d[2]), "+f"(d[3])
        : "r"(a[0]), "r"(a[1]), "r"(a[2]), "r"(a[3]), "r"(b0), "r"(b1));
}
__device__ __forceinline__ uint32_t smem_to_u32(const void* p) {
    uint32_t a;
    asm("{ .reg .u64 t; cvta.to.shared.u64 t, %1; cvt.u32.u64 %0, t; }" : "=r"(a) : "l"(p));
    return a;
}
#define CP16(dst, src) \
    asm volatile("cp.async.cg.shared.global [%0], [%1], 16;" :: "r"(dst), "l"(src))
#define CP16Z(dst, src, sz) \
    asm volatile("cp.async.cg.shared.global [%0], [%1], 16, %2;" :: "r"(dst), "l"(src), "r"(sz))
#define CP_COMMIT() asm volatile("cp.async.commit_group;" ::: "memory")
#define CP_WAIT0()  asm volatile("cp.async.wait_group 0;" ::: "memory")
#define CP_WAIT1()  asm volatile("cp.async.wait_group 1;" ::: "memory")

// ===================== init (bit-matched constants) =====================
__device__ __forceinline__ float erfinv_xla(float x) {
    float w = -log1pf(-__fmul_rn(x, x));
    float p;
    if (w < 5.0f) {
        w = w - 2.5f;
        p = 2.81022636e-08f;
        p = fmaf(p, w, 3.43273939e-07f);
        p = fmaf(p, w, -3.5233877e-06f);
        p = fmaf(p, w, -4.39150654e-06f);
        p = fmaf(p, w, 0.00021858087f);
        p = fmaf(p, w, -0.00125372503f);
        p = fmaf(p, w, -0.00417768164f);
        p = fmaf(p, w, 0.246640727f);
        p = fmaf(p, w, 1.50140941f);
    } else {
        w = sqrtf(w) - 3.0f;
        p = -0.000200214257f;
        p = fmaf(p, w, 0.000100950558f);
        p = fmaf(p, w, 0.00134934322f);
        p = fmaf(p, w, -0.00367342844f);
        p = fmaf(p, w, 0.00573950773f);
        p = fmaf(p, w, -0.0076224613f);
        p = fmaf(p, w, 0.00943887047f);
        p = fmaf(p, w, 1.00167406f);
        p = fmaf(p, w, 2.83297682f);
    }
    return p * x;
}

__global__ void init_freqs(float inv_g) {
    int n = threadIdx.x;
    if (n >= HDS * NF) return;
    float alpha0 = powf(inv_g, 1.0f);
    float alpha1 = powf(inv_g, 2.0f);
    float fi = (float)(n + 1);
    float z0 = fmodf(__fmul_rn(fi, alpha0), 1.0f);
    float z1 = fmodf(__fmul_rn(fi, alpha1), 1.0f);
    float d0 = erfinv_xla(__fmul_rn(2.0f, z0) - 1.0f);
    float d1 = erfinv_xla(__fmul_rn(2.0f, z1) - 1.0f);
    float nrm = sqrtf(__fadd_rn(__fmul_rn(d0, d0), __fmul_rn(d1, d1)));
    d0 = __fdiv_rn(d0, nrm);
    d1 = __fdiv_rn(d1, nrm);
    int f = n % NF;
    float t = __fmul_rn((float)f, (1.0f / 31.0f));
    float omega = __fmul_rn(0.1f, powf(10000.0f, t));
    g_freqs[n * 2 + 0] = __fmul_rn(d0, omega);
    g_freqs[n * 2 + 1] = __fmul_rn(d1, omega);
}

__global__ void init_trig() {
    int idx = blockIdx.x * blockDim.x + threadIdx.x;
    if (idx >= SEQL * HDS * NF) return;
    int s = idx / (HDS * NF);
    int r = idx % (HDS * NF);
    float c0 = 0.f, c1 = 0.f;
    if (s > 0) {
        int p = s - 1;
        int xi = p % 32, yi = p / 32;
        c0 = __fmul_rn(__fdiv_rn((float)xi, 31.0f), 2.0f) - 1.0f;
        c1 = __fmul_rn(__fdiv_rn((float)yi, 31.0f), 2.0f) - 1.0f;
    }
    float th = __fadd_rn(__fmul_rn(g_freqs[r * 2 + 0], c0), __fmul_rn(g_freqs[r * 2 + 1], c1));
    g_cos[idx] = cosf(th);
    g_sin[idx] = sinf(th);
}

// ===================== one-shot W pack =====================
__global__ void __launch_bounds__(256) pack_w_kernel(
    const float* __restrict__ Wq, const float* __restrict__ Wk,
    const float* __restrict__ Wv, const float* __restrict__ Wo)
{
    int idx = blockIdx.x * 256 + threadIdx.x;
    if (idx >= 4 * 72 * 256) return;
    int ks = idx & 3;
    int n = (idx >> 2) & 63;
    int r2 = idx >> 8;
    int mat = r2 / 72;
    int rem = r2 % 72;
    int cb = rem / 12, c2 = rem % 12;
    const float* W = (mat == 0) ? Wq : (mat == 1) ? Wk : (mat == 2) ? Wv : Wo;
    int colbase = cb * 64, k0 = c2 * 32;
    float wv[8];
#pragma unroll
    for (int j = 0; j < 8; j++)
        wv[j] = W[(size_t)(k0 + 8 * ks + j) * EMB + colbase + n];
    uint32_t hi[8], lo[8];
#pragma unroll
    for (int j = 0; j < 8; j++) {
        hi[j] = f2tf32(wv[j]);
        lo[j] = f2tf32(wv[j] - __uint_as_float(hi[j]));
    }
    uint4* dst = g_wp + (size_t)r2 * 1280 + n * 20 + ks * 4;
    dst[0] = make_uint4(hi[0], hi[4], lo[0], lo[4]);
    dst[1] = make_uint4(hi[1], hi[5], lo[1], lo[5]);
    dst[2] = make_uint4(hi[2], hi[6], lo[2], lo[6]);
    dst[3] = make_uint4(hi[3], hi[7], lo[3], lo[7]);
}

// ===================== tensorized GEMM v5: 2-pass (x tf32, W hi/lo) =========
#define GBUF2_W 7424
#define GXW_OFF 2304
#define GEMM_SMEM (2 * GBUF2_W * 4)   // 59392 B

struct GemmAcc { float o[8][4]; };

__device__ __forceinline__ void gemm_issue_v4(
    const float* src, const uint4* wp, int row0, int c2,
    uint32_t sbase, int buf, int tid)
{
    uint32_t base = sbase + (buf ? GBUF2_W * 4 : 0);
#pragma unroll
    for (int u = 0; u < 4; u++) {
        int idx = tid + 128 * u;
        int rr = idx >> 3, c4 = idx & 7;
        int gr = row0 + rr;
        int ok = (gr < ROWS);
        int gc = ok ? gr : (ROWS - 1);
        uint32_t dst = base + (rr * 36 + 4 * c4) * 4;
        const char* s = (const char*)(src + (size_t)gc * EMB + c2 * 32 + 4 * c4);
        CP16Z(dst, s, ok ? 16 : 0);
    }
    const char* ws = (const char*)(wp + (size_t)c2 * 1280);
    uint32_t wd = base + GXW_OFF * 4;
#pragma unroll
    for (int i = 0; i < 10; i++) {
        int off = (tid + 128 * i) * 16;
        CP16(wd + off, ws + off);
    }
}

__device__ __forceinline__ void gemm_core_v5(
    const float* __restrict__ src, const uint4* __restrict__ wp,
    int row0, float* sm, GemmAcc& A)
{
    int tid = threadIdx.x;
    int wid = tid >> 5, lane = tid & 31;
    int g = lane >> 2, tig = lane & 3;
    int wrow = wid * 16;
    uint32_t sbase = smem_to_u32(sm);

    gemm_issue_v4(src, wp, row0, 0, sbase, 0, tid);
    CP_COMMIT();

#pragma unroll
    for (int c2 = 0; c2 < 12; c2++) {
        if (c2 < 11) {
            gemm_issue_v4(src, wp, row0, c2 + 1, sbase, (c2 + 1) & 1, tid);
            CP_COMMIT();
            CP_WAIT1();
        } else {
            CP_WAIT0();
        }
        __syncthreads();

        float* xs = sm + ((c2 & 1) ? GBUF2_W : 0);
        uint4* Wp = (uint4*)(xs + GXW_OFF);
#pragma unroll
        for (int ks = 0; ks < 4; ks++) {
            uint32_t ahi[4];
            ahi[0] = f2tf32(xs[(wrow + g) * 36 + 8 * ks + tig]);
            ahi[1] = f2tf32(xs[(wrow + g + 8) * 36 + 8 * ks + tig]);
            ahi[2] = f2tf32(xs[(wrow + g) * 36 + 8 * ks + tig + 4]);
            ahi[3] = f2tf32(xs[(wrow + g + 8) * 36 + 8 * ks + tig + 4]);
#pragma unroll
            for (int nb = 0; nb < 8; nb++) {
                uint4 w4 = Wp[(nb * 8 + g) * 20 + ks * 4 + tig];
                mma_tf32(A.o[nb], ahi, w4.x, w4.y);
                mma_tf32(A.o[nb], ahi, w4.z, w4.w);
            }
        }
        __syncthreads();
    }
}

__global__ void __launch_bounds__(128, 3) qkv_mma_kernel(const float* __restrict__ x)
{
    extern __shared__ float sm[];
    int tid = threadIdx.x;
    int wid = tid >> 5, lane = tid & 31;
    int g = lane >> 2, tig = lane & 3;
    int wrow = wid * 16;
    int rb = blockIdx.x, h = blockIdx.y, z = blockIdx.z;
    int row0 = rb * 64;
    const uint4* wp = g_wp + ((size_t)z * 6 + h) * 12 * 1280;

    GemmAcc A;
#pragma unroll
    for (int nb = 0; nb < 8; nb++)
#pragma unroll
        for (int j = 0; j < 4; j++) A.o[nb][j] = 0.f;

    gemm_core_v5(x, wp, row0, sm, A);

    if (z == 0) {
        // Q: RoPE, store fp32 (attn re-scales and converts)
#pragma unroll
        for (int nb = 0; nb < 4; nb++)
#pragma unroll
            for (int jj = 0; jj < 4; jj++) {
                int gr = row0 + wrow + g + 8 * (jj >> 1);
                if (gr >= ROWS) continue;
                int b = gr / SEQL, s = gr % SEQL;
                int f = 8 * nb + 2 * tig + (jj & 1);
                float cv = g_cos[(s * HDS + h) * NF + f];
                float sv = g_sin[(s * HDS + h) * NF + f];
                float lov = A.o[nb][jj], hiv = A.o[nb + 4][jj];
                float* dst = g_q + ((size_t)(b * HDS + h) * SEQL + s) * HD;
                dst[f]      = lov * cv - hiv * sv;
                dst[f + 32] = lov * sv + hiv * cv;
            }
    } else if (z == 1) {
        // K: RoPE -> tf32 -> packed fragment layout (shfl pairs col f with f+4)
#pragma unroll
        for (int nb = 0; nb < 4; nb++)
#pragma unroll
            for (int jj = 0; jj < 4; jj++) {
                int gr = row0 + wrow + g + 8 * (jj >> 1);
                bool ok = (gr < ROWS);
                int b = ok ? gr / SEQL : 0;
                int s = ok ? gr % SEQL : 0;
                int f = 8 * nb + 2 * tig + (jj & 1);
                float cv = g_cos[(s * HDS + h) * NF + f];
                float sv = g_sin[(s * HDS + h) * NF + f];
                float lov = A.o[nb][jj], hiv = A.o[nb + 4][jj];
                uint32_t hA = f2tf32(lov * cv - hiv * sv);     // col f
                uint32_t hB = f2tf32(lov * sv + hiv * cv);     // col f+32
                uint32_t pA = __shfl_xor_sync(0xffffffffu, hA, 2);  // col f+4
                uint32_t pB = __shfl_xor_sync(0xffffffffu, hB, 2);  // col f+36
                if (ok && tig < 2) {
                    uint2* kb = g_kp + ((size_t)(b * HDS + h) * NT + (s >> 6)) * 2304
                                + (s & 63) * 36;
                    int tigk = 2 * tig + (jj & 1);
                    kb[nb * 4 + tigk]       = make_uint2(hA, pA);
                    kb[(nb + 4) * 4 + tigk] = make_uint2(hB, pB);
                }
            }
    } else {
        // V: tf32, padded layout, adjacent-col uint2
#pragma unroll
        for (int nb = 0; nb < 8; nb++)
#pragma unroll
            for (int jp = 0; jp < 2; jp++) {
                int gr = row0 + wrow + g + 8 * jp;
                if (gr >= ROWS) continue;
                int b = gr / SEQL, s = gr % SEQL;
                uint32_t* vb = g_vp + ((size_t)(b * HDS + h) * NT + (s >> 6)) * 4608
                               + (s & 63) * 72;
                *(uint2*)(vb + nb * 8 + 2 * tig) =
                    make_uint2(f2tf32(A.o[nb][2 * jp]), f2tf32(A.o[nb][2 * jp + 1]));
            }
    }
}

__global__ void __launch_bounds__(128, 3) proj_mma_kernel(
    const float* __restrict__ bo, float* __restrict__ out)
{
    extern __shared__ float sm[];
    int tid = threadIdx.x;
    int wid = tid >> 5, lane = tid & 31;
    int g = lane >> 2, tig = lane & 3;
    int wrow = wid * 16;
    int rb = blockIdx.x, cb = blockIdx.y;
    int row0 = rb * 64, colbase = cb * 64;
    const uint4* wp = g_wp + ((size_t)3 * 6 + cb) * 12 * 1280;

    GemmAcc A;
#pragma unroll
    for (int nb = 0; nb < 8; nb++)
#pragma unroll
        for (int j = 0; j < 4; j++) A.o[nb][j] = 0.f;

    gemm_core_v5(g_ao, wp, row0, sm, A);

#pragma unroll
    for (int nb = 0; nb < 8; nb++)
#pragma unroll
        for (int jj = 0; jj < 4; jj++) {
            int gr = row0 + wrow + g + 8 * (jj >> 1);
            if (gr >= ROWS) continue;
            int col = 8 * nb + 2 * tig + (jj & 1);
            out[(size_t)gr * EMB + colbase + col] = A.o[nb][jj] + bo[colbase + col];
        }
}

// ===================== Flash attention (cp.async pipelined) =================
#define PS_OFF 0
#define KP_OFF 4352
#define V0_OFF 8960
#define V1_OFF 13568
#define ATTN_SMEM (18176 * 4)   // 72704 B

__global__ void __launch_bounds__(128, 3) attn_mma_kernel() {
    extern __shared__ float sm[];
    float* Ps = sm + PS_OFF;
    uint32_t sbase = smem_to_u32(sm);

    int tid = threadIdx.x;
    int wid = tid >> 5, lane = tid & 31;
    int g = lane >> 2, tig = lane & 3;
    int wrow = wid * 16;
    int qb = blockIdx.x, bh = blockIdx.y;

    const float* Q = g_q + (size_t)bh * SEQL * HD;
    const char* gk = (const char*)(g_kp + (size_t)bh * NT * 2304);
    const char* gv = (const char*)(g_vp + (size_t)bh * NT * 4608);

    const uint32_t KPA = sbase + KP_OFF * 4;
    const uint32_t VA[2] = { sbase + V0_OFF * 4, sbase + V1_OFF * 4 };

#pragma unroll
    for (int i = 0; i < 9; i++) {
        int off = (tid + 128 * i) * 16;
        CP16(KPA + off, gk + off);
        CP16(VA[0] + off, gv + off);
    }
    CP_COMMIT();

#pragma unroll
    for (int u = 0; u < 8; u++) {
        int idx = tid + 128 * u;
        int rr = idx >> 4, c4 = idx & 15;
        int s = qb * 64 + rr;
        float4 v = make_float4(0.f, 0.f, 0.f, 0.f);
        if (s < SEQL) v = *(const float4*)(Q + (size_t)s * HD + c4 * 4);
        v.x *= 0.125f; v.y *= 0.125f; v.z *= 0.125f; v.w *= 0.125f;
        *(float4*)(Ps + rr * 68 + c4 * 4) = v;
    }
    __syncthreads();

    uint32_t qhi[8][4];
#pragma unroll
    for (int ks = 0; ks < 8; ks++) {
#pragma unroll
        for (int j = 0; j < 4; j++) {
            int rr = wrow + g + (j & 1) * 8;
            int cc = 8 * ks + tig + (j >> 1) * 4;
            qhi[ks][j] = f2tf32(Ps[rr * 68 + cc]);
        }
    }

    float o[8][4] = {};
    float m0 = -INFINITY, m1 = -INFINITY, l0 = 0.f, l1 = 0.f;

    for (int t = 0; t < NT; t++) {
        CP_WAIT0();
        __syncthreads();

        if (t < NT - 1) {
            const char* vsrc = gv + (size_t)(t + 1) * 4608 * 4;
            uint32_t vdst = VA[(t + 1) & 1];
#pragma unroll
            for (int i = 0; i < 9; i++) {
                int off = (tid + 128 * i) * 16;
                CP16(vdst + off, vsrc + off);
            }
            CP_COMMIT();
        }

        uint2* Kp = (uint2*)(sm + KP_OFF);
        float s_[8][4] = {};
#pragma unroll
        for (int ks = 0; ks < 8; ks++) {
#pragma unroll
            for (int nb = 0; nb < 8; nb++) {
                uint2 kk = Kp[(nb * 8 + g) * 36 + ks * 4 + tig];
                mma_tf32(s_[nb], qhi[ks], kk.x, kk.y);
            }
        }
        __syncthreads();

        if (t < NT - 1) {
            const char* ksrc = gk + (size_t)(t + 1) * 2304 * 8;
#pragma unroll
            for (int i = 0; i < 9; i++) {
                int off = (tid + 128 * i) * 16;
                CP16(KPA + off, ksrc + off);
            }
            CP_COMMIT();
        }

        if (t == NT - 1) {
#pragma unroll
            for (int nb = 0; nb < 8; nb++) {
                int c = 1024 + nb * 8 + 2 * tig;
                if (c >= SEQL)     { s_[nb][0] = -INFINITY; s_[nb][2] = -INFINITY; }
                if (c + 1 >= SEQL) { s_[nb][1] = -INFINITY; s_[nb][3] = -INFINITY; }
            }
        }

        float rm0 = -INFINITY, rm1 = -INFINITY;
#pragma unroll
        for (int nb = 0; nb < 8; nb++) {
            rm0 = fmaxf(rm0, fmaxf(s_[nb][0], s_[nb][1]));
            rm1 = fmaxf(rm1, fmaxf(s_[nb][2], s_[nb][3]));
        }
        rm0 = fmaxf(rm0, __shfl_xor_sync(0xffffffffu, rm0, 1));
        rm0 = fmaxf(rm0, __shfl_xor_sync(0xffffffffu, rm0, 2));
        rm1 = fmaxf(rm1, __shfl_xor_sync(0xffffffffu, rm1, 1));
        rm1 = fmaxf(rm1, __shfl_xor_sync(0xffffffffu, rm1, 2));
        float nm0 = fmaxf(m0, rm0), nm1 = fmaxf(m1, rm1);
        float corr0 = __expf(m0 - nm0), corr1 = __expf(m1 - nm1);
        m0 = nm0; m1 = nm1;

        float rs0 = 0.f, rs1 = 0.f;
#pragma unroll
        for (int nb = 0; nb < 8; nb++) {
            s_[nb][0] = __expf(s_[nb][0] - m0);
            s_[nb][1] = __expf(s_[nb][1] - m0);
            s_[nb][2] = __expf(s_[nb][2] - m1);
            s_[nb][3] = __expf(s_[nb][3] - m1);
            rs0 += s_[nb][0] + s_[nb][1];
            rs1 += s_[nb][2] + s_[nb][3];
        }
        rs0 += __shfl_xor_sync(0xffffffffu, rs0, 1);
        rs0 += __shfl_xor_sync(0xffffffffu, rs0, 2);
        rs1 += __shfl_xor_sync(0xffffffffu, rs1, 1);
        rs1 += __shfl_xor_sync(0xffffffffu, rs1, 2);
        l0 = l0 * corr0 + rs0;
        l1 = l1 * corr1 + rs1;

#pragma unroll
        for (int nb = 0; nb < 8; nb++) {
            o[nb][0] *= corr0; o[nb][1] *= corr0;
            o[nb][2] *= corr1; o[nb][3] *= corr1;
        }

#pragma unroll
        for (int nb = 0; nb < 8; nb++) {
            *(float2*)(Ps + (wrow + g) * 68 + nb * 8 + 2 * tig)     = make_float2(s_[nb][0], s_[nb][1]);
            *(float2*)(Ps + (wrow + g + 8) * 68 + nb * 8 + 2 * tig) = make_float2(s_[nb][2], s_[nb][3]);
        }
        __syncwarp();

        uint32_t* Vs = (uint32_t*)(sm + ((t & 1) ? V1_OFF : V0_OFF));
#pragma unroll
        for (int ks = 0; ks < 8; ks++) {
            uint32_t pa[4];
            pa[0] = f2tf32(Ps[(wrow + g) * 68 + 8 * ks + tig]);
            pa[1] = f2tf32(Ps[(wrow + g + 8) * 68 + 8 * ks + tig]);
            pa[2] = f2tf32(Ps[(wrow + g) * 68 + 8 * ks + tig + 4]);
            pa[3] = f2tf32(Ps[(wrow + g + 8) * 68 + 8 * ks + tig + 4]);
#pragma unroll
            for (int nb = 0; nb < 8; nb++) {
                int r0 = 8 * ks + tig;
                int cc = nb * 8 + g;
                mma_tf32(o[nb], pa, Vs[r0 * 72 + cc], Vs[(r0 + 4) * 72 + cc]);
            }
        }
    }

    float inv0 = 1.0f / l0, inv1 = 1.0f / l1;
    int b = bh / HDS, h = bh % HDS;
    int s0 = qb * 64 + wrow + g;
    int s1 = s0 + 8;
#pragma unroll
    for (int nb = 0; nb < 8; nb++) {
        int cc = nb * 8 + 2 * tig;
        if (s0 < SEQL) {
            float* dst = g_ao + ((size_t)b * SEQL + s0) * EMB + h * HD + cc;
            *(float2*)dst = make_float2(o[nb][0] * inv0, o[nb][1] * inv0);
        }
        if (s1 < SEQL) {
            float* dst = g_ao + ((size_t)b * SEQL + s1) * EMB + h * HD + cc;
            *(float2*)dst = make_float2(o[nb][2] * inv1, o[nb][3] * inv1);
        }
    }
}

// ===================== launch =====================
extern "C" void kernel_launch(void* const* d_in, const int* in_sizes, int n_in,
                              void* d_out, int out_size)
{
    const float* x  = (const float*)d_in[0];
    const float* Wq = (const float*)d_in[1];
    const float* Wk = (const float*)d_in[2];
    const float* Wv = (const float*)d_in[3];
    const float* Wo = (const float*)d_in[4];
    const float* bo = (const float*)d_in[5];
    float* out = (float*)d_out;

    double xg = 2.0;
    for (int it = 0; it < 10; ++it) xg = pow(1.0 + xg, 1.0 / 3.0);
    float inv_g = (float)(1.0 / xg);

    cudaFuncSetAttribute(attn_mma_kernel,
                         cudaFuncAttributeMaxDynamicSharedMemorySize, ATTN_SMEM);
    cudaFuncSetAttribute(qkv_mma_kernel,
                         cudaFuncAttributeMaxDynamicSharedMemorySize, GEMM_SMEM);
    cudaFuncSetAttribute(proj_mma_kernel,
                         cudaFuncAttributeMaxDynamicSharedMemorySize, GEMM_SMEM);

    init_freqs<<<1, 192>>>(inv_g);
    init_trig<<<(SEQL * HDS * NF + 255) / 256, 256>>>();
    pack_w_kernel<<<(4 * 72 * 256 + 255) / 256, 256>>>(Wq, Wk, Wv, Wo);

    dim3 qkv_grid((ROWS + 63) / 64, HDS, 3);
    qkv_mma_kernel<<<qkv_grid, 128, GEMM_SMEM>>>(x);

    dim3 attn_grid(NT, BHN);
    attn_mma_kernel<<<attn_grid, 128, ATTN_SMEM>>>();

    dim3 proj_grid((ROWS + 63) / 64, EMB / 64);
    proj_mma_kernel<<<proj_grid, 128, GEMM_SMEM>>>(bo, out);
}

// round 15
// speedup vs baseline: 1.4616x; 1.0602x over previous
#include <cuda_runtime.h>
#include <math.h>
#include <stdint.h>

#define BB 16
#define SEQL 1025
#define EMB 384
#define HDS 6
#define HD 64
#define NF 32
#define ROWS (BB*SEQL)
#define BHN (BB*HDS)
#define NT 17
#define NPAD (NT*64)

__device__ float g_q[(size_t)BHN*SEQL*HD];
__device__ float g_ao[(size_t)ROWS*EMB];
__device__ float g_cos[SEQL*HDS*NF];
__device__ float g_sin[SEQL*HDS*NF];
__device__ float g_freqs[HDS*NF*2];
__device__ uint2    g_kp[(size_t)BHN*NT*2304];
__device__ uint32_t g_vp[(size_t)BHN*NT*4608];
__device__ uint4    g_wp[(size_t)4*6*12*1280];

// ===================== mma.sync helpers =====================
__device__ __forceinline__ uint32_t f2tf32(float x) {
    uint32_t r;
    asm("cvt.rna.tf32.f32 %0, %1;" : "=r"(r) : "f"(x));
    return r;
}
__device__ __forceinline__ void mma_tf32(float* d, const uint32_t* a,
                                         uint32_t b0, uint32_t b1) {
    asm volatile(
        "mma.sync.aligned.m16n8k8.row.col.f32.tf32.tf32.f32 "
        "{%0,%1,%2,%3}, {%4,%5,%6,%7}, {%8,%9}, {%0,%1,%2,%3};"
        : "+f"(d[0]), "+f"(d[1]), "+f"(d[2]), "+f"(d[3])
        : "r"(a[0]), "r"(a[1]), "r"(a[2]), "r"(a[3]), "r"(b0), "r"(b1));
}
__device__ __forceinline__ uint32_t smem_to_u32(const void* p) {
    uint32_t a;
    asm("{ .reg .u64 t; cvta.to.shared.u64 t, %1; cvt.u32.u64 %0, t; }" : "=r"(a) : "l"(p));
    return a;
}
#define CP16(dst, src) \
    asm volatile("cp.async.cg.shared.global [%0], [%1], 16;" :: "r"(dst), "l"(src))
#define CP16Z(dst, src, sz) \
    asm volatile("cp.async.cg.shared.global [%0], [%1], 16, %2;" :: "r"(dst), "l"(src), "r"(sz))
#define CP_COMMIT() asm volatile("cp.async.commit_group;" ::: "memory")
#define CP_WAIT0()  asm volatile("cp.async.wait_group 0;" ::: "memory")
#define CP_WAIT1()  asm volatile("cp.async.wait_group 1;" ::: "memory")

// ===================== init (bit-matched constants) =====================
__device__ __forceinline__ float erfinv_xla(float x) {
    float w = -log1pf(-__fmul_rn(x, x));
    float p;
    if (w < 5.0f) {
        w = w - 2.5f;
        p = 2.81022636e-08f;
        p = fmaf(p, w, 3.43273939e-07f);
        p = fmaf(p, w, -3.5233877e-06f);
        p = fmaf(p, w, -4.39150654e-06f);
        p = fmaf(p, w, 0.00021858087f);
        p = fmaf(p, w, -0.00125372503f);
        p = fmaf(p, w, -0.00417768164f);
        p = fmaf(p, w, 0.246640727f);
        p = fmaf(p, w, 1.50140941f);
    } else {
        w = sqrtf(w) - 3.0f;
        p = -0.000200214257f;
        p = fmaf(p, w, 0.000100950558f);
        p = fmaf(p, w, 0.00134934322f);
        p = fmaf(p, w, -0.00367342844f);
        p = fmaf(p, w, 0.00573950773f);
        p = fmaf(p, w, -0.0076224613f);
        p = fmaf(p, w, 0.00943887047f);
        p = fmaf(p, w, 1.00167406f);
        p = fmaf(p, w, 2.83297682f);
    }
    return p * x;
}

__global__ void init_freqs(float inv_g) {
    int n = threadIdx.x;
    if (n >= HDS * NF) return;
    float alpha0 = powf(inv_g, 1.0f);
    float alpha1 = powf(inv_g, 2.0f);
    float fi = (float)(n + 1);
    float z0 = fmodf(__fmul_rn(fi, alpha0), 1.0f);
    float z1 = fmodf(__fmul_rn(fi, alpha1), 1.0f);
    float d0 = erfinv_xla(__fmul_rn(2.0f, z0) - 1.0f);
    float d1 = erfinv_xla(__fmul_rn(2.0f, z1) - 1.0f);
    float nrm = sqrtf(__fadd_rn(__fmul_rn(d0, d0), __fmul_rn(d1, d1)));
    d0 = __fdiv_rn(d0, nrm);
    d1 = __fdiv_rn(d1, nrm);
    int f = n % NF;
    float t = __fmul_rn((float)f, (1.0f / 31.0f));
    float omega = __fmul_rn(0.1f, powf(10000.0f, t));
    g_freqs[n * 2 + 0] = __fmul_rn(d0, omega);
    g_freqs[n * 2 + 1] = __fmul_rn(d1, omega);
}

__global__ void init_trig() {
    int idx = blockIdx.x * blockDim.x + threadIdx.x;
    if (idx >= SEQL * HDS * NF) return;
    int s = idx / (HDS * NF);
    int r = idx % (HDS * NF);
    float c0 = 0.f, c1 = 0.f;
    if (s > 0) {
        int p = s - 1;
        int xi = p % 32, yi = p / 32;
        c0 = __fmul_rn(__fdiv_rn((float)xi, 31.0f), 2.0f) - 1.0f;
        c1 = __fmul_rn(__fdiv_rn((float)yi, 31.0f), 2.0f) - 1.0f;
    }
    float th = __fadd_rn(__fmul_rn(g_freqs[r * 2 + 0], c0), __fmul_rn(g_freqs[r * 2 + 1], c1));
    g_cos[idx] = cosf(th);
    g_sin[idx] = sinf(th);
}

// ===================== one-shot W pack =====================
__global__ void __launch_bounds__(256) pack_w_kernel(
    const float* __restrict__ Wq, const float* __restrict__ Wk,
    const float* __restrict__ Wv, const float* __restrict__ Wo)
{
    int idx = blockIdx.x * 256 + threadIdx.x;
    if (idx >= 4 * 72 * 256) return;
    int ks = idx & 3;
    int n = (idx >> 2) & 63;
    int r2 = idx >> 8;
    int mat = r2 / 72;
    int rem = r2 % 72;
    int cb = rem / 12, c2 = rem % 12;
    const float* W = (mat == 0) ? Wq : (mat == 1) ? Wk : (mat == 2) ? Wv : Wo;
    int colbase = cb * 64, k0 = c2 * 32;
    float wv[8];
#pragma unroll
    for (int j = 0; j < 8; j++)
        wv[j] = W[(size_t)(k0 + 8 * ks + j) * EMB + colbase + n];
    uint32_t hi[8], lo[8];
#pragma unroll
    for (int j = 0; j < 8; j++) {
        hi[j] = f2tf32(wv[j]);
        lo[j] = f2tf32(wv[j] - __uint_as_float(hi[j]));
    }
    uint4* dst = g_wp + (size_t)r2 * 1280 + n * 20 + ks * 4;
    dst[0] = make_uint4(hi[0], hi[4], lo[0], lo[4]);
    dst[1] = make_uint4(hi[1], hi[5], lo[1], lo[5]);
    dst[2] = make_uint4(hi[2], hi[6], lo[2], lo[6]);
    dst[3] = make_uint4(hi[3], hi[7], lo[3], lo[7]);
}

// ===================== tensorized GEMM v6: 2x2 warp grid =====================
// CTA tile 64x64, warp tile 32 rows x 32 cols (cols via ncol mapping).
#define GBUF2_W 7424
#define GXW_OFF 2304
#define GEMM_SMEM (2 * GBUF2_W * 4)   // 59392 B

struct GemmAcc { float o[2][4][4]; };

__device__ __forceinline__ int gemm_ncol(int wc, int nb) {
    return wc * 16 + (nb & 1) * 8 + (nb >> 1) * 32;
}

__device__ __forceinline__ void gemm_issue_v4(
    const float* src, const uint4* wp, int row0, int c2,
    uint32_t sbase, int buf, int tid)
{
    uint32_t base = sbase + (buf ? GBUF2_W * 4 : 0);
#pragma unroll
    for (int u = 0; u < 4; u++) {
        int idx = tid + 128 * u;
        int rr = idx >> 3, c4 = idx & 7;
        int gr = row0 + rr;
        int ok = (gr < ROWS);
        int gc = ok ? gr : (ROWS - 1);
        uint32_t dst = base + (rr * 36 + 4 * c4) * 4;
        const char* s = (const char*)(src + (size_t)gc * EMB + c2 * 32 + 4 * c4);
        CP16Z(dst, s, ok ? 16 : 0);
    }
    const char* ws = (const char*)(wp + (size_t)c2 * 1280);
    uint32_t wd = base + GXW_OFF * 4;
#pragma unroll
    for (int i = 0; i < 10; i++) {
        int off = (tid + 128 * i) * 16;
        CP16(wd + off, ws + off);
    }
}

__device__ __forceinline__ void gemm_core_v6(
    const float* __restrict__ src, const uint4* __restrict__ wp,
    int row0, float* sm, GemmAcc& A)
{
    int tid = threadIdx.x;
    int wid = tid >> 5, lane = tid & 31;
    int g = lane >> 2, tig = lane & 3;
    int wr = wid & 1, wc = wid >> 1;
    int wrow = wr * 32;
    uint32_t sbase = smem_to_u32(sm);

    gemm_issue_v4(src, wp, row0, 0, sbase, 0, tid);
    CP_COMMIT();

#pragma unroll
    for (int c2 = 0; c2 < 12; c2++) {
        if (c2 < 11) {
            gemm_issue_v4(src, wp, row0, c2 + 1, sbase, (c2 + 1) & 1, tid);
            CP_COMMIT();
            CP_WAIT1();
        } else {
            CP_WAIT0();
        }
        __syncthreads();

        float* xs = sm + ((c2 & 1) ? GBUF2_W : 0);
        uint4* Wp = (uint4*)(xs + GXW_OFF);
#pragma unroll
        for (int ks = 0; ks < 4; ks++) {
            uint32_t ahi[2][4];
#pragma unroll
            for (int mt = 0; mt < 2; mt++) {
                int rbase = wrow + mt * 16;
                ahi[mt][0] = f2tf32(xs[(rbase + g) * 36 + 8 * ks + tig]);
                ahi[mt][1] = f2tf32(xs[(rbase + g + 8) * 36 + 8 * ks + tig]);
                ahi[mt][2] = f2tf32(xs[(rbase + g) * 36 + 8 * ks + tig + 4]);
                ahi[mt][3] = f2tf32(xs[(rbase + g + 8) * 36 + 8 * ks + tig + 4]);
            }
#pragma unroll
            for (int nb = 0; nb < 4; nb++) {
                uint4 w4 = Wp[(gemm_ncol(wc, nb) + g) * 20 + ks * 4 + tig];
#pragma unroll
                for (int mt = 0; mt < 2; mt++) {
                    mma_tf32(A.o[mt][nb], ahi[mt], w4.x, w4.y);
                    mma_tf32(A.o[mt][nb], ahi[mt], w4.z, w4.w);
                }
            }
        }
        __syncthreads();
    }
}

__global__ void __launch_bounds__(128, 3) qkv_mma_kernel(const float* __restrict__ x)
{
    extern __shared__ float sm[];
    int tid = threadIdx.x;
    int wid = tid >> 5, lane = tid & 31;
    int g = lane >> 2, tig = lane & 3;
    int wr = wid & 1, wc = wid >> 1;
    int wrow = wr * 32;
    int rb = blockIdx.x, h = blockIdx.y, z = blockIdx.z;
    int row0 = rb * 64;
    const uint4* wp = g_wp + ((size_t)z * 6 + h) * 12 * 1280;

    GemmAcc A;
#pragma unroll
    for (int mt = 0; mt < 2; mt++)
#pragma unroll
        for (int nb = 0; nb < 4; nb++)
#pragma unroll
            for (int j = 0; j < 4; j++) A.o[mt][nb][j] = 0.f;

    gemm_core_v6(x, wp, row0, sm, A);

    if (z == 0) {
        // Q: RoPE (pair nb <-> nb+2 holds f and f+32), store fp32
#pragma unroll
        for (int mt = 0; mt < 2; mt++)
#pragma unroll
            for (int nb = 0; nb < 2; nb++)
#pragma unroll
                for (int jj = 0; jj < 4; jj++) {
                    int gr = row0 + wrow + mt * 16 + g + 8 * (jj >> 1);
                    if (gr >= ROWS) continue;
                    int b = gr / SEQL, s = gr % SEQL;
                    int f = wc * 16 + nb * 8 + 2 * tig + (jj & 1);
                    float cv = g_cos[(s * HDS + h) * NF + f];
                    float sv = g_sin[(s * HDS + h) * NF + f];
                    float lov = A.o[mt][nb][jj], hiv = A.o[mt][nb + 2][jj];
                    float* dst = g_q + ((size_t)(b * HDS + h) * SEQL + s) * HD;
                    dst[f]      = lov * cv - hiv * sv;
                    dst[f + 32] = lov * sv + hiv * cv;
                }
    } else if (z == 1) {
        // K: RoPE -> tf32 -> packed fragment layout
#pragma unroll
        for (int mt = 0; mt < 2; mt++)
#pragma unroll
            for (int nb = 0; nb < 2; nb++)
#pragma unroll
                for (int jj = 0; jj < 4; jj++) {
                    int gr = row0 + wrow + mt * 16 + g + 8 * (jj >> 1);
                    bool ok = (gr < ROWS);
                    int b = ok ? gr / SEQL : 0;
                    int s = ok ? gr % SEQL : 0;
                    int f = wc * 16 + nb * 8 + 2 * tig + (jj & 1);
                    float cv = g_cos[(s * HDS + h) * NF + f];
                    float sv = g_sin[(s * HDS + h) * NF + f];
                    float lov = A.o[mt][nb][jj], hiv = A.o[mt][nb + 2][jj];
                    uint32_t hA = f2tf32(lov * cv - hiv * sv);        // col f
                    uint32_t hB = f2tf32(lov * sv + hiv * cv);        // col f+32
                    uint32_t pA = __shfl_xor_sync(0xffffffffu, hA, 2); // col f+4
                    uint32_t pB = __shfl_xor_sync(0xffffffffu, hB, 2); // col f+36
                    if (ok && tig < 2) {
                        uint2* kb = g_kp + ((size_t)(b * HDS + h) * NT + (s >> 6)) * 2304
                                    + (s & 63) * 36;
                        int tigk = 2 * tig + (jj & 1);
                        int ksA = wc * 2 + nb;          // f block (f>>3)
                        kb[ksA * 4 + tigk]       = make_uint2(hA, pA);
                        kb[(ksA + 4) * 4 + tigk] = make_uint2(hB, pB);
                    }
                }
    } else {
        // V: tf32, padded layout, adjacent-col uint2
#pragma unroll
        for (int mt = 0; mt < 2; mt++)
#pragma unroll
            for (int nb = 0; nb < 4; nb++)
#pragma unroll
                for (int jp = 0; jp < 2; jp++) {
                    int gr = row0 + wrow + mt * 16 + g + 8 * jp;
                    if (gr >= ROWS) continue;
                    int b = gr / SEQL, s = gr % SEQL;
                    int col = gemm_ncol(wc, nb) + 2 * tig;
                    uint32_t* vb = g_vp + ((size_t)(b * HDS + h) * NT + (s >> 6)) * 4608
                                   + (s & 63) * 72;
                    *(uint2*)(vb + col) =
                        make_uint2(f2tf32(A.o[mt][nb][2 * jp]), f2tf32(A.o[mt][nb][2 * jp + 1]));
                }
    }
}

__global__ void __launch_bounds__(128, 3) proj_mma_kernel(
    const float* __restrict__ bo, float* __restrict__ out)
{
    extern __shared__ float sm[];
    int tid = threadIdx.x;
    int wid = tid >> 5, lane = tid & 31;
    int g = lane >> 2, tig = lane & 3;
    int wr = wid & 1, wc = wid >> 1;
    int wrow = wr * 32;
    int rb = blockIdx.x, cb = blockIdx.y;
    int row0 = rb * 64, colbase = cb * 64;
    const uint4* wp = g_wp + ((size_t)3 * 6 + cb) * 12 * 1280;

    GemmAcc A;
#pragma unroll
    for (int mt = 0; mt < 2; mt++)
#pragma unroll
        for (int nb = 0; nb < 4; nb++)
#pragma unroll
            for (int j = 0; j < 4; j++) A.o[mt][nb][j] = 0.f;

    gemm_core_v6(g_ao, wp, row0, sm, A);

#pragma unroll
    for (int mt = 0; mt < 2; mt++)
#pragma unroll
        for (int nb = 0; nb < 4; nb++)
#pragma unroll
            for (int jj = 0; jj < 4; jj++) {
                int gr = row0 + wrow + mt * 16 + g + 8 * (jj >> 1);
                if (gr >= ROWS) continue;
                int col = gemm_ncol(wc, nb) + 2 * tig + (jj & 1);
                out[(size_t)gr * EMB + colbase + col] = A.o[mt][nb][jj] + bo[colbase + col];
            }
}

// ===================== Flash attention (cp.async pipelined) =================
#define PS_OFF 0
#define KP_OFF 4352
#define V0_OFF 8960
#define V1_OFF 13568
#define ATTN_SMEM (18176 * 4)   // 72704 B

__global__ void __launch_bounds__(128, 3) attn_mma_kernel() {
    extern __shared__ float sm[];
    float* Ps = sm + PS_OFF;
    uint32_t sbase = smem_to_u32(sm);

    int tid = threadIdx.x;
    int wid = tid >> 5, lane = tid & 31;
    int g = lane >> 2, tig = lane & 3;
    int wrow = wid * 16;
    int qb = blockIdx.x, bh = blockIdx.y;

    const float* Q = g_q + (size_t)bh * SEQL * HD;
    const char* gk = (const char*)(g_kp + (size_t)bh * NT * 2304);
    const char* gv = (const char*)(g_vp + (size_t)bh * NT * 4608);

    const uint32_t KPA = sbase + KP_OFF * 4;
    const uint32_t VA[2] = { sbase + V0_OFF * 4, sbase + V1_OFF * 4 };

#pragma unroll
    for (int i = 0; i < 9; i++) {
        int off = (tid + 128 * i) * 16;
        CP16(KPA + off, gk + off);
        CP16(VA[0] + off, gv + off);
    }
    CP_COMMIT();

#pragma unroll
    for (int u = 0; u < 8; u++) {
        int idx = tid + 128 * u;
        int rr = idx >> 4, c4 = idx & 15;
        int s = qb * 64 + rr;
        float4 v = make_float4(0.f, 0.f, 0.f, 0.f);
        if (s < SEQL) v = *(const float4*)(Q + (size_t)s * HD + c4 * 4);
        v.x *= 0.125f; v.y *= 0.125f; v.z *= 0.125f; v.w *= 0.125f;
        *(float4*)(Ps + rr * 68 + c4 * 4) = v;
    }
    __syncthreads();

    uint32_t qhi[8][4];
#pragma unroll
    for (int ks = 0; ks < 8; ks++) {
#pragma unroll
        for (int j = 0; j < 4; j++) {
            int rr = wrow + g + (j & 1) * 8;
            int cc = 8 * ks + tig + (j >> 1) * 4;
            qhi[ks][j] = f2tf32(Ps[rr * 68 + cc]);
        }
    }

    float o[8][4] = {};
    float m0 = -INFINITY, m1 = -INFINITY, l0 = 0.f, l1 = 0.f;

    for (int t = 0; t < NT; t++) {
        CP_WAIT0();
        __syncthreads();

        if (t < NT - 1) {
            const char* vsrc = gv + (size_t)(t + 1) * 4608 * 4;
            uint32_t vdst = VA[(t + 1) & 1];
#pragma unroll
            for (int i = 0; i < 9; i++) {
                int off = (tid + 128 * i) * 16;
                CP16(vdst + off, vsrc + off);
            }
            CP_COMMIT();
        }

        uint2* Kp = (uint2*)(sm + KP_OFF);
        float s_[8][4] = {};
#pragma unroll
        for (int ks = 0; ks < 8; ks++) {
#pragma unroll
            for (int nb = 0; nb < 8; nb++) {
                uint2 kk = Kp[(nb * 8 + g) * 36 + ks * 4 + tig];
                mma_tf32(s_[nb], qhi[ks], kk.x, kk.y);
            }
        }
        __syncthreads();

        if (t < NT - 1) {
            const char* ksrc = gk + (size_t)(t + 1) * 2304 * 8;
#pragma unroll
            for (int i = 0; i < 9; i++) {
                int off = (tid + 128 * i) * 16;
                CP16(KPA + off, ksrc + off);
            }
            CP_COMMIT();
        }

        if (t == NT - 1) {
#pragma unroll
            for (int nb = 0; nb < 8; nb++) {
                int c = 1024 + nb * 8 + 2 * tig;
                if (c >= SEQL)     { s_[nb][0] = -INFINITY; s_[nb][2] = -INFINITY; }
                if (c + 1 >= SEQL) { s_[nb][1] = -INFINITY; s_[nb][3] = -INFINITY; }
            }
        }

        float rm0 = -INFINITY, rm1 = -INFINITY;
#pragma unroll
        for (int nb = 0; nb < 8; nb++) {
            rm0 = fmaxf(rm0, fmaxf(s_[nb][0], s_[nb][1]));
            rm1 = fmaxf(rm1, fmaxf(s_[nb][2], s_[nb][3]));
        }
        rm0 = fmaxf(rm0, __shfl_xor_sync(0xffffffffu, rm0, 1));
        rm0 = fmaxf(rm0, __shfl_xor_sync(0xffffffffu, rm0, 2));
        rm1 = fmaxf(rm1, __shfl_xor_sync(0xffffffffu, rm1, 1));
        rm1 = fmaxf(rm1, __shfl_xor_sync(0xffffffffu, rm1, 2));
        float nm0 = fmaxf(m0, rm0), nm1 = fmaxf(m1, rm1);
        float corr0 = __expf(m0 - nm0), corr1 = __expf(m1 - nm1);
        m0 = nm0; m1 = nm1;

        float rs0 = 0.f, rs1 = 0.f;
#pragma unroll
        for (int nb = 0; nb < 8; nb++) {
            s_[nb][0] = __expf(s_[nb][0] - m0);
            s_[nb][1] = __expf(s_[nb][1] - m0);
            s_[nb][2] = __expf(s_[nb][2] - m1);
            s_[nb][3] = __expf(s_[nb][3] - m1);
            rs0 += s_[nb][0] + s_[nb][1];
            rs1 += s_[nb][2] + s_[nb][3];
        }
        rs0 += __shfl_xor_sync(0xffffffffu, rs0, 1);
        rs0 += __shfl_xor_sync(0xffffffffu, rs0, 2);
        rs1 += __shfl_xor_sync(0xffffffffu, rs1, 1);
        rs1 += __shfl_xor_sync(0xffffffffu, rs1, 2);
        l0 = l0 * corr0 + rs0;
        l1 = l1 * corr1 + rs1;

#pragma unroll
        for (int nb = 0; nb < 8; nb++) {
            o[nb][0] *= corr0; o[nb][1] *= corr0;
            o[nb][2] *= corr1; o[nb][3] *= corr1;
        }

#pragma unroll
        for (int nb = 0; nb < 8; nb++) {
            *(float2*)(Ps + (wrow + g) * 68 + nb * 8 + 2 * tig)     = make_float2(s_[nb][0], s_[nb][1]);
            *(float2*)(Ps + (wrow + g + 8) * 68 + nb * 8 + 2 * tig) = make_float2(s_[nb][2], s_[nb][3]);
        }
        __syncwarp();

        uint32_t* Vs = (uint32_t*)(sm + ((t & 1) ? V1_OFF : V0_OFF));
#pragma unroll
        for (int ks = 0; ks < 8; ks++) {
            uint32_t pa[4];
            pa[0] = f2tf32(Ps[(wrow + g) * 68 + 8 * ks + tig]);
            pa[1] = f2tf32(Ps[(wrow + g + 8) * 68 + 8 * ks + tig]);
            pa[2] = f2tf32(Ps[(wrow + g) * 68 + 8 * ks + tig + 4]);
            pa[3] = f2tf32(Ps[(wrow + g + 8) * 68 + 8 * ks + tig + 4]);
#pragma unroll
            for (int nb = 0; nb < 8; nb++) {
                int r0 = 8 * ks + tig;
                int cc = nb * 8 + g;
                mma_tf32(o[nb], pa, Vs[r0 * 72 + cc], Vs[(r0 + 4) * 72 + cc]);
            }
        }
    }

    float inv0 = 1.0f / l0, inv1 = 1.0f / l1;
    int b = bh / HDS, h = bh % HDS;
    int s0 = qb * 64 + wrow + g;
    int s1 = s0 + 8;
#pragma unroll
    for (int nb = 0; nb < 8; nb++) {
        int cc = nb * 8 + 2 * tig;
        if (s0 < SEQL) {
            float* dst = g_ao + ((size_t)b * SEQL + s0) * EMB + h * HD + cc;
            *(float2*)dst = make_float2(o[nb][0] * inv0, o[nb][1] * inv0);
        }
        if (s1 < SEQL) {
            float* dst = g_ao + ((size_t)b * SEQL + s1) * EMB + h * HD + cc;
            *(float2*)dst = make_float2(o[nb][2] * inv1, o[nb][3] * inv1);
        }
    }
}

// ===================== launch =====================
extern "C" void kernel_launch(void* const* d_in, const int* in_sizes, int n_in,
                              void* d_out, int out_size)
{
    const float* x  = (const float*)d_in[0];
    const float* Wq = (const float*)d_in[1];
    const float* Wk = (const float*)d_in[2];
    const float* Wv = (const float*)d_in[3];
    const float* Wo = (const float*)d_in[4];
    const float* bo = (const float*)d_in[5];
    float* out = (float*)d_out;

    double xg = 2.0;
    for (int it = 0; it < 10; ++it) xg = pow(1.0 + xg, 1.0 / 3.0);
    float inv_g = (float)(1.0 / xg);

    cudaFuncSetAttribute(attn_mma_kernel,
                         cudaFuncAttributeMaxDynamicSharedMemorySize, ATTN_SMEM);
    cudaFuncSetAttribute(qkv_mma_kernel,
                         cudaFuncAttributeMaxDynamicSharedMemorySize, GEMM_SMEM);
    cudaFuncSetAttribute(proj_mma_kernel,
                         cudaFuncAttributeMaxDynamicSharedMemorySize, GEMM_SMEM);

    init_freqs<<<1, 192>>>(inv_g);
    init_trig<<<(SEQL * HDS * NF + 255) / 256, 256>>>();
    pack_w_kernel<<<(4 * 72 * 256 + 255) / 256, 256>>>(Wq, Wk, Wv, Wo);

    dim3 qkv_grid((ROWS + 63) / 64, HDS, 3);
    qkv_mma_kernel<<<qkv_grid, 128, GEMM_SMEM>>>(x);

    dim3 attn_grid(NT, BHN);
    attn_mma_kernel<<<attn_grid, 128, ATTN_SMEM>>>();

    dim3 proj_grid((ROWS + 63) / 64, EMB / 64);
    proj_mma_kernel<<<proj_grid, 128, GEMM_SMEM>>>(bo, out);
}

// round 16
// speedup vs baseline: 1.4725x; 1.0074x over previous
#include <cuda_runtime.h>
#include <math.h>
#include <stdint.h>

#define BB 16
#define SEQL 1025
#define EMB 384
#define HDS 6
#define HD 64
#define NF 32
#define ROWS (BB*SEQL)
#define BHN (BB*HDS)
#define NT 17
#define NPAD (NT*64)

__device__ float g_q[(size_t)BHN*SEQL*HD];
__device__ float g_ao[(size_t)ROWS*EMB];
__device__ float g_cos[SEQL*HDS*NF];
__device__ float g_sin[SEQL*HDS*NF];
__device__ float g_freqs[HDS*NF*2];
__device__ uint2    g_kp[(size_t)BHN*NT*2304];
// V pair-packed: per tile 4608 words; uint2 slot [col*36 + ks*4 + tig] =
// (V[8ks+tig][col], V[8ks+tig+4][col]); zero-init covers pad rows
__device__ uint32_t g_vp[(size_t)BHN*NT*4608];
__device__ uint4    g_wp[(size_t)4*6*12*1280];

// ===================== mma.sync helpers =====================
__device__ __forceinline__ uint32_t f2tf32(float x) {
    uint32_t r;
    asm("cvt.rna.tf32.f32 %0, %1;" : "=r"(r) : "f"(x));
    return r;
}
__device__ __forceinline__ void mma_tf32(float* d, const uint32_t* a,
                                         uint32_t b0, uint32_t b1) {
    asm volatile(
        "mma.sync.aligned.m16n8k8.row.col.f32.tf32.tf32.f32 "
        "{%0,%1,%2,%3}, {%4,%5,%6,%7}, {%8,%9}, {%0,%1,%2,%3};"
        : "+f"(d[0]), "+f"(d[1]), "+f"(d[2]), "+f"(d[3])
        : "r"(a[0]), "r"(a[1]), "r"(a[2]), "r"(a[3]), "r"(b0), "r"(b1));
}
__device__ __forceinline__ uint32_t smem_to_u32(const void* p) {
    uint32_t a;
    asm("{ .reg .u64 t; cvta.to.shared.u64 t, %1; cvt.u32.u64 %0, t; }" : "=r"(a) : "l"(p));
    return a;
}
#define CP16(dst, src) \
    asm volatile("cp.async.cg.shared.global [%0], [%1], 16;" :: "r"(dst), "l"(src))
#define CP16Z(dst, src, sz) \
    asm volatile("cp.async.cg.shared.global [%0], [%1], 16, %2;" :: "r"(dst), "l"(src), "r"(sz))
#define CP_COMMIT() asm volatile("cp.async.commit_group;" ::: "memory")
#define CP_WAIT0()  asm volatile("cp.async.wait_group 0;" ::: "memory")
#define CP_WAIT1()  asm volatile("cp.async.wait_group 1;" ::: "memory")

// ===================== init (bit-matched constants) =====================
__device__ __forceinline__ float erfinv_xla(float x) {
    float w = -log1pf(-__fmul_rn(x, x));
    float p;
    if (w < 5.0f) {
        w = w - 2.5f;
        p = 2.81022636e-08f;
        p = fmaf(p, w, 3.43273939e-07f);
        p = fmaf(p, w, -3.5233877e-06f);
        p = fmaf(p, w, -4.39150654e-06f);
        p = fmaf(p, w, 0.00021858087f);
        p = fmaf(p, w, -0.00125372503f);
        p = fmaf(p, w, -0.00417768164f);
        p = fmaf(p, w, 0.246640727f);
        p = fmaf(p, w, 1.50140941f);
    } else {
        w = sqrtf(w) - 3.0f;
        p = -0.000200214257f;
        p = fmaf(p, w, 0.000100950558f);
        p = fmaf(p, w, 0.00134934322f);
        p = fmaf(p, w, -0.00367342844f);
        p = fmaf(p, w, 0.00573950773f);
        p = fmaf(p, w, -0.0076224613f);
        p = fmaf(p, w, 0.00943887047f);
        p = fmaf(p, w, 1.00167406f);
        p = fmaf(p, w, 2.83297682f);
    }
    return p * x;
}

__global__ void init_freqs(float inv_g) {
    int n = threadIdx.x;
    if (n >= HDS * NF) return;
    float alpha0 = powf(inv_g, 1.0f);
    float alpha1 = powf(inv_g, 2.0f);
    float fi = (float)(n + 1);
    float z0 = fmodf(__fmul_rn(fi, alpha0), 1.0f);
    float z1 = fmodf(__fmul_rn(fi, alpha1), 1.0f);
    float d0 = erfinv_xla(__fmul_rn(2.0f, z0) - 1.0f);
    float d1 = erfinv_xla(__fmul_rn(2.0f, z1) - 1.0f);
    float nrm = sqrtf(__fadd_rn(__fmul_rn(d0, d0), __fmul_rn(d1, d1)));
    d0 = __fdiv_rn(d0, nrm);
    d1 = __fdiv_rn(d1, nrm);
    int f = n % NF;
    float t = __fmul_rn((float)f, (1.0f / 31.0f));
    float omega = __fmul_rn(0.1f, powf(10000.0f, t));
    g_freqs[n * 2 + 0] = __fmul_rn(d0, omega);
    g_freqs[n * 2 + 1] = __fmul_rn(d1, omega);
}

__global__ void init_trig() {
    int idx = blockIdx.x * blockDim.x + threadIdx.x;
    if (idx >= SEQL * HDS * NF) return;
    int s = idx / (HDS * NF);
    int r = idx % (HDS * NF);
    float c0 = 0.f, c1 = 0.f;
    if (s > 0) {
        int p = s - 1;
        int xi = p % 32, yi = p / 32;
        c0 = __fmul_rn(__fdiv_rn((float)xi, 31.0f), 2.0f) - 1.0f;
        c1 = __fmul_rn(__fdiv_rn((float)yi, 31.0f), 2.0f) - 1.0f;
    }
    float th = __fadd_rn(__fmul_rn(g_freqs[r * 2 + 0], c0), __fmul_rn(g_freqs[r * 2 + 1], c1));
    g_cos[idx] = cosf(th);
    g_sin[idx] = sinf(th);
}

// ===================== one-shot W pack =====================
__global__ void __launch_bounds__(256) pack_w_kernel(
    const float* __restrict__ Wq, const float* __restrict__ Wk,
    const float* __restrict__ Wv, const float* __restrict__ Wo)
{
    int idx = blockIdx.x * 256 + threadIdx.x;
    if (idx >= 4 * 72 * 256) return;
    int ks = idx & 3;
    int n = (idx >> 2) & 63;
    int r2 = idx >> 8;
    int mat = r2 / 72;
    int rem = r2 % 72;
    int cb = rem / 12, c2 = rem % 12;
    const float* W = (mat == 0) ? Wq : (mat == 1) ? Wk : (mat == 2) ? Wv : Wo;
    int colbase = cb * 64, k0 = c2 * 32;
    float wv[8];
#pragma unroll
    for (int j = 0; j < 8; j++)
        wv[j] = W[(size_t)(k0 + 8 * ks + j) * EMB + colbase + n];
    uint32_t hi[8], lo[8];
#pragma unroll
    for (int j = 0; j < 8; j++) {
        hi[j] = f2tf32(wv[j]);
        lo[j] = f2tf32(wv[j] - __uint_as_float(hi[j]));
    }
    uint4* dst = g_wp + (size_t)r2 * 1280 + n * 20 + ks * 4;
    dst[0] = make_uint4(hi[0], hi[4], lo[0], lo[4]);
    dst[1] = make_uint4(hi[1], hi[5], lo[1], lo[5]);
    dst[2] = make_uint4(hi[2], hi[6], lo[2], lo[6]);
    dst[3] = make_uint4(hi[3], hi[7], lo[3], lo[7]);
}

// ===================== tensorized GEMM v6: 2x2 warp grid =====================
#define GBUF2_W 7424
#define GXW_OFF 2304
#define GEMM_SMEM (2 * GBUF2_W * 4)   // 59392 B

struct GemmAcc { float o[2][4][4]; };

__device__ __forceinline__ int gemm_ncol(int wc, int nb) {
    return wc * 16 + (nb & 1) * 8 + (nb >> 1) * 32;
}

__device__ __forceinline__ void gemm_issue_v4(
    const float* src, const uint4* wp, int row0, int c2,
    uint32_t sbase, int buf, int tid)
{
    uint32_t base = sbase + (buf ? GBUF2_W * 4 : 0);
#pragma unroll
    for (int u = 0; u < 4; u++) {
        int idx = tid + 128 * u;
        int rr = idx >> 3, c4 = idx & 7;
        int gr = row0 + rr;
        int ok = (gr < ROWS);
        int gc = ok ? gr : (ROWS - 1);
        uint32_t dst = base + (rr * 36 + 4 * c4) * 4;
        const char* s = (const char*)(src + (size_t)gc * EMB + c2 * 32 + 4 * c4);
        CP16Z(dst, s, ok ? 16 : 0);
    }
    const char* ws = (const char*)(wp + (size_t)c2 * 1280);
    uint32_t wd = base + GXW_OFF * 4;
#pragma unroll
    for (int i = 0; i < 10; i++) {
        int off = (tid + 128 * i) * 16;
        CP16(wd + off, ws + off);
    }
}

__device__ __forceinline__ void gemm_core_v6(
    const float* __restrict__ src, const uint4* __restrict__ wp,
    int row0, float* sm, GemmAcc& A)
{
    int tid = threadIdx.x;
    int wid = tid >> 5, lane = tid & 31;
    int g = lane >> 2, tig = lane & 3;
    int wr = wid & 1, wc = wid >> 1;
    int wrow = wr * 32;
    uint32_t sbase = smem_to_u32(sm);

    gemm_issue_v4(src, wp, row0, 0, sbase, 0, tid);
    CP_COMMIT();

#pragma unroll
    for (int c2 = 0; c2 < 12; c2++) {
        if (c2 < 11) {
            gemm_issue_v4(src, wp, row0, c2 + 1, sbase, (c2 + 1) & 1, tid);
            CP_COMMIT();
            CP_WAIT1();
        } else {
            CP_WAIT0();
        }
        __syncthreads();

        float* xs = sm + ((c2 & 1) ? GBUF2_W : 0);
        uint4* Wp = (uint4*)(xs + GXW_OFF);
#pragma unroll
        for (int ks = 0; ks < 4; ks++) {
            uint32_t ahi[2][4];
#pragma unroll
            for (int mt = 0; mt < 2; mt++) {
                int rbase = wrow + mt * 16;
                ahi[mt][0] = f2tf32(xs[(rbase + g) * 36 + 8 * ks + tig]);
                ahi[mt][1] = f2tf32(xs[(rbase + g + 8) * 36 + 8 * ks + tig]);
                ahi[mt][2] = f2tf32(xs[(rbase + g) * 36 + 8 * ks + tig + 4]);
                ahi[mt][3] = f2tf32(xs[(rbase + g + 8) * 36 + 8 * ks + tig + 4]);
            }
#pragma unroll
            for (int nb = 0; nb < 4; nb++) {
                uint4 w4 = Wp[(gemm_ncol(wc, nb) + g) * 20 + ks * 4 + tig];
#pragma unroll
                for (int mt = 0; mt < 2; mt++) {
                    mma_tf32(A.o[mt][nb], ahi[mt], w4.x, w4.y);
                    mma_tf32(A.o[mt][nb], ahi[mt], w4.z, w4.w);
                }
            }
        }
        __syncthreads();
    }
}

__global__ void __launch_bounds__(128, 3) qkv_mma_kernel(const float* __restrict__ x)
{
    extern __shared__ float sm[];
    int tid = threadIdx.x;
    int wid = tid >> 5, lane = tid & 31;
    int g = lane >> 2, tig = lane & 3;
    int wr = wid & 1, wc = wid >> 1;
    int wrow = wr * 32;
    int rb = blockIdx.x, h = blockIdx.y, z = blockIdx.z;
    int row0 = rb * 64;
    const uint4* wp = g_wp + ((size_t)z * 6 + h) * 12 * 1280;

    GemmAcc A;
#pragma unroll
    for (int mt = 0; mt < 2; mt++)
#pragma unroll
        for (int nb = 0; nb < 4; nb++)
#pragma unroll
            for (int j = 0; j < 4; j++) A.o[mt][nb][j] = 0.f;

    gemm_core_v6(x, wp, row0, sm, A);

    if (z == 0) {
        // Q: RoPE (pair nb <-> nb+2 holds f and f+32), store fp32
#pragma unroll
        for (int mt = 0; mt < 2; mt++)
#pragma unroll
            for (int nb = 0; nb < 2; nb++)
#pragma unroll
                for (int jj = 0; jj < 4; jj++) {
                    int gr = row0 + wrow + mt * 16 + g + 8 * (jj >> 1);
                    if (gr >= ROWS) continue;
                    int b = gr / SEQL, s = gr % SEQL;
                    int f = wc * 16 + nb * 8 + 2 * tig + (jj & 1);
                    float cv = g_cos[(s * HDS + h) * NF + f];
                    float sv = g_sin[(s * HDS + h) * NF + f];
                    float lov = A.o[mt][nb][jj], hiv = A.o[mt][nb + 2][jj];
                    float* dst = g_q + ((size_t)(b * HDS + h) * SEQL + s) * HD;
                    dst[f]      = lov * cv - hiv * sv;
                    dst[f + 32] = lov * sv + hiv * cv;
                }
    } else if (z == 1) {
        // K: RoPE -> tf32 -> packed fragment layout
#pragma unroll
        for (int mt = 0; mt < 2; mt++)
#pragma unroll
            for (int nb = 0; nb < 2; nb++)
#pragma unroll
                for (int jj = 0; jj < 4; jj++) {
                    int gr = row0 + wrow + mt * 16 + g + 8 * (jj >> 1);
                    bool ok = (gr < ROWS);
                    int b = ok ? gr / SEQL : 0;
                    int s = ok ? gr % SEQL : 0;
                    int f = wc * 16 + nb * 8 + 2 * tig + (jj & 1);
                    float cv = g_cos[(s * HDS + h) * NF + f];
                    float sv = g_sin[(s * HDS + h) * NF + f];
                    float lov = A.o[mt][nb][jj], hiv = A.o[mt][nb + 2][jj];
                    uint32_t hA = f2tf32(lov * cv - hiv * sv);        // col f
                    uint32_t hB = f2tf32(lov * sv + hiv * cv);        // col f+32
                    uint32_t pA = __shfl_xor_sync(0xffffffffu, hA, 2); // col f+4
                    uint32_t pB = __shfl_xor_sync(0xffffffffu, hB, 2); // col f+36
                    if (ok && tig < 2) {
                        uint2* kb = g_kp + ((size_t)(b * HDS + h) * NT + (s >> 6)) * 2304
                                    + (s & 63) * 36;
                        int tigk = 2 * tig + (jj & 1);
                        int ksA = wc * 2 + nb;          // f block (f>>3)
                        kb[ksA * 4 + tigk]       = make_uint2(hA, pA);
                        kb[(ksA + 4) * 4 + tigk] = make_uint2(hB, pB);
                    }
                }
    } else {
        // V: tf32 -> pair-packed layout, scalar word writes
#pragma unroll
        for (int mt = 0; mt < 2; mt++)
#pragma unroll
            for (int nb = 0; nb < 4; nb++)
#pragma unroll
                for (int jj = 0; jj < 4; jj++) {
                    int gr = row0 + wrow + mt * 16 + g + 8 * (jj >> 1);
                    if (gr >= ROWS) continue;
                    int b = gr / SEQL, s = gr % SEQL;
                    int col = gemm_ncol(wc, nb) + 2 * tig + (jj & 1);
                    int r = s & 63;
                    int woff = 2 * (col * 36 + (r >> 3) * 4 + (r & 3)) + ((r & 7) >> 2);
                    uint32_t* vb = g_vp + ((size_t)(b * HDS + h) * NT + (s >> 6)) * 4608;
                    vb[woff] = f2tf32(A.o[mt][nb][jj]);
                }
    }
}

__global__ void __launch_bounds__(128, 3) proj_mma_kernel(
    const float* __restrict__ bo, float* __restrict__ out)
{
    extern __shared__ float sm[];
    int tid = threadIdx.x;
    int wid = tid >> 5, lane = tid & 31;
    int g = lane >> 2, tig = lane & 3;
    int wr = wid & 1, wc = wid >> 1;
    int wrow = wr * 32;
    int rb = blockIdx.x, cb = blockIdx.y;
    int row0 = rb * 64, colbase = cb * 64;
    const uint4* wp = g_wp + ((size_t)3 * 6 + cb) * 12 * 1280;

    GemmAcc A;
#pragma unroll
    for (int mt = 0; mt < 2; mt++)
#pragma unroll
        for (int nb = 0; nb < 4; nb++)
#pragma unroll
            for (int j = 0; j < 4; j++) A.o[mt][nb][j] = 0.f;

    gemm_core_v6(g_ao, wp, row0, sm, A);

#pragma unroll
    for (int mt = 0; mt < 2; mt++)
#pragma unroll
        for (int nb = 0; nb < 4; nb++)
#pragma unroll
            for (int jj = 0; jj < 4; jj++) {
                int gr = row0 + wrow + mt * 16 + g + 8 * (jj >> 1);
                if (gr >= ROWS) continue;
                int col = gemm_ncol(wc, nb) + 2 * tig + (jj & 1);
                out[(size_t)gr * EMB + colbase + col] = A.o[mt][nb][jj] + bo[colbase + col];
            }
}

// ===================== Flash attention (cp.async pipelined) =================
#define PS_OFF 0
#define KP_OFF 4352
#define V0_OFF 8960
#define V1_OFF 13568
#define ATTN_SMEM (18176 * 4)   // 72704 B

__global__ void __launch_bounds__(128, 3) attn_mma_kernel() {
    extern __shared__ float sm[];
    float* Ps = sm + PS_OFF;
    uint32_t sbase = smem_to_u32(sm);

    int tid = threadIdx.x;
    int wid = tid >> 5, lane = tid & 31;
    int g = lane >> 2, tig = lane & 3;
    int wrow = wid * 16;
    int qb = blockIdx.x, bh = blockIdx.y;

    const float* Q = g_q + (size_t)bh * SEQL * HD;
    const char* gk = (const char*)(g_kp + (size_t)bh * NT * 2304);
    const char* gv = (const char*)(g_vp + (size_t)bh * NT * 4608);

    const uint32_t KPA = sbase + KP_OFF * 4;
    const uint32_t VA[2] = { sbase + V0_OFF * 4, sbase + V1_OFF * 4 };

#pragma unroll
    for (int i = 0; i < 9; i++) {
        int off = (tid + 128 * i) * 16;
        CP16(KPA + off, gk + off);
        CP16(VA[0] + off, gv + off);
    }
    CP_COMMIT();

#pragma unroll
    for (int u = 0; u < 8; u++) {
        int idx = tid + 128 * u;
        int rr = idx >> 4, c4 = idx & 15;
        int s = qb * 64 + rr;
        float4 v = make_float4(0.f, 0.f, 0.f, 0.f);
        if (s < SEQL) v = *(const float4*)(Q + (size_t)s * HD + c4 * 4);
        v.x *= 0.125f; v.y *= 0.125f; v.z *= 0.125f; v.w *= 0.125f;
        *(float4*)(Ps + rr * 68 + c4 * 4) = v;
    }
    __syncthreads();

    uint32_t qhi[8][4];
#pragma unroll
    for (int ks = 0; ks < 8; ks++) {
#pragma unroll
        for (int j = 0; j < 4; j++) {
            int rr = wrow + g + (j & 1) * 8;
            int cc = 8 * ks + tig + (j >> 1) * 4;
            qhi[ks][j] = f2tf32(Ps[rr * 68 + cc]);
        }
    }

    float o[8][4] = {};
    float m0 = -INFINITY, m1 = -INFINITY, l0 = 0.f, l1 = 0.f;

    for (int t = 0; t < NT; t++) {
        CP_WAIT0();
        __syncthreads();

        if (t < NT - 1) {
            const char* vsrc = gv + (size_t)(t + 1) * 4608 * 4;
            uint32_t vdst = VA[(t + 1) & 1];
#pragma unroll
            for (int i = 0; i < 9; i++) {
                int off = (tid + 128 * i) * 16;
                CP16(vdst + off, vsrc + off);
            }
            CP_COMMIT();
        }

        uint2* Kp = (uint2*)(sm + KP_OFF);
        float s_[8][4] = {};
#pragma unroll
        for (int ks = 0; ks < 8; ks++) {
#pragma unroll
            for (int nb = 0; nb < 8; nb++) {
                uint2 kk = Kp[(nb * 8 + g) * 36 + ks * 4 + tig];
                mma_tf32(s_[nb], qhi[ks], kk.x, kk.y);
            }
        }
        __syncthreads();

        if (t < NT - 1) {
            const char* ksrc = gk + (size_t)(t + 1) * 2304 * 8;
#pragma unroll
            for (int i = 0; i < 9; i++) {
                int off = (tid + 128 * i) * 16;
                CP16(KPA + off, ksrc + off);
            }
            CP_COMMIT();
        }

        if (t == NT - 1) {
#pragma unroll
            for (int nb = 0; nb < 8; nb++) {
                int c = 1024 + nb * 8 + 2 * tig;
                if (c >= SEQL)     { s_[nb][0] = -INFINITY; s_[nb][2] = -INFINITY; }
                if (c + 1 >= SEQL) { s_[nb][1] = -INFINITY; s_[nb][3] = -INFINITY; }
            }
        }

        float rm0 = -INFINITY, rm1 = -INFINITY;
#pragma unroll
        for (int nb = 0; nb < 8; nb++) {
            rm0 = fmaxf(rm0, fmaxf(s_[nb][0], s_[nb][1]));
            rm1 = fmaxf(rm1, fmaxf(s_[nb][2], s_[nb][3]));
        }
        rm0 = fmaxf(rm0, __shfl_xor_sync(0xffffffffu, rm0, 1));
        rm0 = fmaxf(rm0, __shfl_xor_sync(0xffffffffu, rm0, 2));
        rm1 = fmaxf(rm1, __shfl_xor_sync(0xffffffffu, rm1, 1));
        rm1 = fmaxf(rm1, __shfl_xor_sync(0xffffffffu, rm1, 2));
        float nm0 = fmaxf(m0, rm0), nm1 = fmaxf(m1, rm1);
        float corr0 = __expf(m0 - nm0), corr1 = __expf(m1 - nm1);
        m0 = nm0; m1 = nm1;

        float rs0 = 0.f, rs1 = 0.f;
#pragma unroll
        for (int nb = 0; nb < 8; nb++) {
            s_[nb][0] = __expf(s_[nb][0] - m0);
            s_[nb][1] = __expf(s_[nb][1] - m0);
            s_[nb][2] = __expf(s_[nb][2] - m1);
            s_[nb][3] = __expf(s_[nb][3] - m1);
            rs0 += s_[nb][0] + s_[nb][1];
            rs1 += s_[nb][2] + s_[nb][3];
        }
        rs0 += __shfl_xor_sync(0xffffffffu, rs0, 1);
        rs0 += __shfl_xor_sync(0xffffffffu, rs0, 2);
        rs1 += __shfl_xor_sync(0xffffffffu, rs1, 1);
        rs1 += __shfl_xor_sync(0xffffffffu, rs1, 2);
        l0 = l0 * corr0 + rs0;
        l1 = l1 * corr1 + rs1;

#pragma unroll
        for (int nb = 0; nb < 8; nb++) {
            o[nb][0] *= corr0; o[nb][1] *= corr0;
            o[nb][2] *= corr1; o[nb][3] *= corr1;
        }

#pragma unroll
        for (int nb = 0; nb < 8; nb++) {
            *(float2*)(Ps + (wrow + g) * 68 + nb * 8 + 2 * tig)     = make_float2(s_[nb][0], s_[nb][1]);
            *(float2*)(Ps + (wrow + g + 8) * 68 + nb * 8 + 2 * tig) = make_float2(s_[nb][2], s_[nb][3]);
        }
        __syncwarp();

        uint2* Vp2 = (uint2*)(sm + ((t & 1) ? V1_OFF : V0_OFF));
#pragma unroll
        for (int ks = 0; ks < 8; ks++) {
            uint32_t pa[4];
            pa[0] = f2tf32(Ps[(wrow + g) * 68 + 8 * ks + tig]);
            pa[1] = f2tf32(Ps[(wrow + g + 8) * 68 + 8 * ks + tig]);
            pa[2] = f2tf32(Ps[(wrow + g) * 68 + 8 * ks + tig + 4]);
            pa[3] = f2tf32(Ps[(wrow + g + 8) * 68 + 8 * ks + tig + 4]);
#pragma unroll
            for (int nb = 0; nb < 8; nb++) {
                uint2 vv = Vp2[(nb * 8 + g) * 36 + ks * 4 + tig];
                mma_tf32(o[nb], pa, vv.x, vv.y);
            }
        }
    }

    float inv0 = 1.0f / l0, inv1 = 1.0f / l1;
    int b = bh / HDS, h = bh % HDS;
    int s0 = qb * 64 + wrow + g;
    int s1 = s0 + 8;
#pragma unroll
    for (int nb = 0; nb < 8; nb++) {
        int cc = nb * 8 + 2 * tig;
        if (s0 < SEQL) {
            float* dst = g_ao + ((size_t)b * SEQL + s0) * EMB + h * HD + cc;
            *(float2*)dst = make_float2(o[nb][0] * inv0, o[nb][1] * inv0);
        }
        if (s1 < SEQL) {
            float* dst = g_ao + ((size_t)b * SEQL + s1) * EMB + h * HD + cc;
            *(float2*)dst = make_float2(o[nb][2] * inv1, o[nb][3] * inv1);
        }
    }
}

// ===================== launch =====================
extern "C" void kernel_launch(void* const* d_in, const int* in_sizes, int n_in,
                              void* d_out, int out_size)
{
    const float* x  = (const float*)d_in[0];
    const float* Wq = (const float*)d_in[1];
    const float* Wk = (const float*)d_in[2];
    const float* Wv = (const float*)d_in[3];
    const float* Wo = (const float*)d_in[4];
    const float* bo = (const float*)d_in[5];
    float* out = (float*)d_out;

    double xg = 2.0;
    for (int it = 0; it < 10; ++it) xg = pow(1.0 + xg, 1.0 / 3.0);
    float inv_g = (float)(1.0 / xg);

    cudaFuncSetAttribute(attn_mma_kernel,
                         cudaFuncAttributeMaxDynamicSharedMemorySize, ATTN_SMEM);
    cudaFuncSetAttribute(qkv_mma_kernel,
                         cudaFuncAttributeMaxDynamicSharedMemorySize, GEMM_SMEM);
    cudaFuncSetAttribute(proj_mma_kernel,
                         cudaFuncAttributeMaxDynamicSharedMemorySize, GEMM_SMEM);

    init_freqs<<<1, 192>>>(inv_g);
    init_trig<<<(SEQL * HDS * NF + 255) / 256, 256>>>();
    pack_w_kernel<<<(4 * 72 * 256 + 255) / 256, 256>>>(Wq, Wk, Wv, Wo);

    dim3 qkv_grid((ROWS + 63) / 64, HDS, 3);
    qkv_mma_kernel<<<qkv_grid, 128, GEMM_SMEM>>>(x);

    dim3 attn_grid(NT, BHN);
    attn_mma_kernel<<<attn_grid, 128, ATTN_SMEM>>>();

    dim3 proj_grid((ROWS + 63) / 64, EMB / 64);
    proj_mma_kernel<<<proj_grid, 128, GEMM_SMEM>>>(bo, out);
}